// round 1
// baseline (speedup 1.0000x reference)
#include <cuda_runtime.h>
#include <cstdint>

#define N_MAX   50000
#define E_MAX   1700000   // 1.6M edges + 50k self loops
#define WMAX    512
#define N_GRAPHS 64

// ---------------- scratch (device globals: no runtime alloc allowed) --------
__device__ float g_bufA[(size_t)N_MAX * WMAX];
__device__ float g_bufB[(size_t)N_MAX * WMAX];
__device__ float g_bufC[(size_t)N_MAX * WMAX];
__device__ float g_dinv[N_MAX];
__device__ int   g_cnt[N_MAX];
__device__ int   g_rowptr[N_MAX + 1];
__device__ int   g_cur[N_MAX];
__device__ int   g_col[E_MAX];
__device__ float g_wgt[E_MAX];
__device__ float g_pool[N_GRAPHS * 32];
__device__ int   g_pcnt[N_GRAPHS];
__device__ int   g_is64;

// ---------------- index load helper (int32 vs int64 input) ------------------
__device__ __forceinline__ int ld_idx(const void* p, long i) {
    if (g_is64) return (int)((const long long*)p)[i];
    return ((const int*)p)[i];
}

// Detect whether edge_index is int64 (little-endian: odd int32 words all zero
// since values < 50000) or int32.
__global__ void detect_kernel(const void* edge) {
    const int* p = (const int*)edge;
    bool is64 = true;
    for (int i = 0; i < 8; i++)
        if (p[2 * i + 1] != 0) is64 = false;
    g_is64 = is64 ? 1 : 0;
}

// ---------------- degree / norm / CSR build ---------------------------------
__global__ void init_cnt_kernel(int n) {
    int i = blockIdx.x * blockDim.x + threadIdx.x;
    if (i < n) g_cnt[i] = 1;   // self loop
}

__global__ void count_kernel(const void* edge, int E) {
    int e = blockIdx.x * blockDim.x + threadIdx.x;
    if (e < E) {
        int dst = ld_idx(edge, (long)E + e);
        atomicAdd(&g_cnt[dst], 1);
    }
}

__global__ void dinv_kernel(int n) {
    int i = blockIdx.x * blockDim.x + threadIdx.x;
    if (i < n) g_dinv[i] = rsqrtf((float)g_cnt[i]);
}

// single-block exclusive scan of g_cnt -> g_rowptr, g_cur
__global__ void scan_kernel(int n) {
    __shared__ int sh[1024];
    __shared__ int carry_s;
    int tid = threadIdx.x;
    if (tid == 0) carry_s = 0;
    __syncthreads();
    for (int base = 0; base < n; base += 1024) {
        int i = base + tid;
        int v = (i < n) ? g_cnt[i] : 0;
        sh[tid] = v;
        __syncthreads();
        for (int off = 1; off < 1024; off <<= 1) {
            int t = (tid >= off) ? sh[tid - off] : 0;
            __syncthreads();
            sh[tid] += t;
            __syncthreads();
        }
        int carry = carry_s;
        if (i < n) {
            int excl = carry + sh[tid] - v;
            g_rowptr[i] = excl;
            g_cur[i]    = excl;
        }
        __syncthreads();
        if (tid == 1023) carry_s = carry + sh[1023];
        __syncthreads();
    }
    if (tid == 0) g_rowptr[n] = carry_s;
}

__global__ void fill_edges_kernel(const void* edge, int E) {
    int e = blockIdx.x * blockDim.x + threadIdx.x;
    if (e < E) {
        int src = ld_idx(edge, e);
        int dst = ld_idx(edge, (long)E + e);
        int pos = atomicAdd(&g_cur[dst], 1);
        g_col[pos] = src;
        g_wgt[pos] = g_dinv[src] * g_dinv[dst];
    }
}

__global__ void fill_loops_kernel(int n) {
    int i = blockIdx.x * blockDim.x + threadIdx.x;
    if (i < n) {
        int pos = atomicAdd(&g_cur[i], 1);
        g_col[pos] = i;
        g_wgt[pos] = g_dinv[i] * g_dinv[i];
    }
}

// ---------------- SpMM: out[i,:] = sum_j w_ij * in[col_j,:] (+bias, act) ----
// One block per node; NR registers per thread; W = NR*BD exact.
template <int NR, int BD>
__global__ void spmm_kernel(const float* __restrict__ in, float* __restrict__ out,
                            const float* __restrict__ bias, int act) {
    constexpr int W = NR * BD;
    int node = blockIdx.x;
    int tid  = threadIdx.x;
    int s = g_rowptr[node];
    int e = g_rowptr[node + 1];
    float acc[NR];
#pragma unroll
    for (int r = 0; r < NR; r++) acc[r] = 0.f;

    int p = s;
    for (; p + 1 < e; p += 2) {
        int   c0 = g_col[p],   c1 = g_col[p + 1];
        float w0 = g_wgt[p],   w1 = g_wgt[p + 1];
        const float* r0 = in + (long)c0 * W;
        const float* r1 = in + (long)c1 * W;
#pragma unroll
        for (int r = 0; r < NR; r++)
            acc[r] += w0 * r0[tid + r * BD] + w1 * r1[tid + r * BD];
    }
    if (p < e) {
        int   c0 = g_col[p];
        float w0 = g_wgt[p];
        const float* r0 = in + (long)c0 * W;
#pragma unroll
        for (int r = 0; r < NR; r++)
            acc[r] += w0 * r0[tid + r * BD];
    }

#pragma unroll
    for (int r = 0; r < NR; r++) {
        int col = tid + r * BD;
        float v = acc[r];
        if (bias) v += bias[col];
        if (act == 1) v = fmaxf(v, 0.f);
        else if (act == 2) v = (v > 0.f) ? v : 0.01f * v;
        out[(long)node * W + col] = v;
    }
}

// ---------------- Tiled SGEMM: C = A(MxK) * W(KxN) (+bias, act) -------------
// BM=128, BN=64, BK=16, 256 threads, 8x4 per thread.
__global__ __launch_bounds__(256) void gemm_kernel(
    const float* __restrict__ A, const float* __restrict__ Wm,
    const float* __restrict__ bias, float* __restrict__ C,
    int M, int K, int N, int act)
{
    __shared__ float As[16][128];
    __shared__ float Bs[16][64];
    int tid = threadIdx.x;
    int tx = tid & 15, ty = tid >> 4;
    int bn = blockIdx.x * 64;
    int bm = blockIdx.y * 128;

    float acc[8][4];
#pragma unroll
    for (int i = 0; i < 8; i++)
#pragma unroll
        for (int j = 0; j < 4; j++) acc[i][j] = 0.f;

    for (int k0 = 0; k0 < K; k0 += 16) {
        // A tile: 128x16 = 512 float4, 2 per thread, store transposed
#pragma unroll
        for (int q = 0; q < 2; q++) {
            int fi  = tid + q * 256;
            int row = fi >> 2;
            int jj  = fi & 3;
            int grow = bm + row;
            float4 v = make_float4(0.f, 0.f, 0.f, 0.f);
            if (grow < M) v = *(const float4*)(A + (long)grow * K + k0 + jj * 4);
            As[jj * 4 + 0][row] = v.x;
            As[jj * 4 + 1][row] = v.y;
            As[jj * 4 + 2][row] = v.z;
            As[jj * 4 + 3][row] = v.w;
        }
        // B tile: 16x64 = 256 float4, 1 per thread
        {
            int brow = tid >> 4;
            int bc   = tid & 15;
            int gcol = bn + bc * 4;
            float4 v = make_float4(0.f, 0.f, 0.f, 0.f);
            if (gcol < N) v = *(const float4*)(Wm + (long)(k0 + brow) * N + gcol);
            *(float4*)&Bs[brow][bc * 4] = v;
        }
        __syncthreads();
#pragma unroll
        for (int k = 0; k < 16; k++) {
            float a[8], b[4];
#pragma unroll
            for (int i = 0; i < 8; i++) a[i] = As[k][ty + 16 * i];
#pragma unroll
            for (int j = 0; j < 4; j++) b[j] = Bs[k][tx + 16 * j];
#pragma unroll
            for (int i = 0; i < 8; i++)
#pragma unroll
                for (int j = 0; j < 4; j++) acc[i][j] += a[i] * b[j];
        }
        __syncthreads();
    }

#pragma unroll
    for (int i = 0; i < 8; i++) {
        int row = bm + ty + 16 * i;
        if (row >= M) continue;
#pragma unroll
        for (int j = 0; j < 4; j++) {
            int col = bn + tx + 16 * j;
            if (col >= N) continue;
            float v = acc[i][j];
            if (bias) v += bias[col];
            if (act == 1) v = fmaxf(v, 0.f);
            else if (act == 2) v = (v > 0.f) ? v : 0.01f * v;
            C[(long)row * N + col] = v;
        }
    }
}

// ---------------- mean pool over graphs -------------------------------------
__global__ void zero_pool_kernel() {
    int i = blockIdx.x * blockDim.x + threadIdx.x;
    if (i < N_GRAPHS * 32) g_pool[i] = 0.f;
    if (i < N_GRAPHS) g_pcnt[i] = 0;
}

__global__ void pool_cnt_kernel(const void* batch, int n) {
    int i = blockIdx.x * blockDim.x + threadIdx.x;
    if (i < n) {
        int b = ld_idx(batch, i);
        atomicAdd(&g_pcnt[b], 1);
    }
}

__global__ void pool_sum_kernel(const float* __restrict__ h, const void* batch, int n) {
    int idx = blockIdx.x * blockDim.x + threadIdx.x;
    if (idx < n * 32) {
        int node = idx >> 5;
        int c    = idx & 31;
        int b = ld_idx(batch, node);
        atomicAdd(&g_pool[b * 32 + c], h[(long)node * 32 + c]);
    }
}

__global__ void pool_fin_kernel(float* out) {
    int i = blockIdx.x * blockDim.x + threadIdx.x;
    if (i < N_GRAPHS * 32) {
        int b = i >> 5;
        float cnt = (float)g_pcnt[b];
        out[i] = g_pool[i] / fmaxf(cnt, 1.0f);
    }
}

// ---------------- host driver ------------------------------------------------
static inline int cdiv(int a, int b) { return (a + b - 1) / b; }

static void spmm_launch(const float* in, float* out, int W,
                        const float* bias, int act, int n) {
    if (W == 32)       spmm_kernel<1, 32><<<n, 32>>>(in, out, bias, act);
    else if (W == 128) spmm_kernel<1, 128><<<n, 128>>>(in, out, bias, act);
    else if (W == 256) spmm_kernel<2, 128><<<n, 128>>>(in, out, bias, act);
    else if (W == 384) spmm_kernel<3, 128><<<n, 128>>>(in, out, bias, act);
    else               spmm_kernel<4, 128><<<n, 128>>>(in, out, bias, act);
}

static void gemm_launch(const float* A, const float* Wm, const float* bias,
                        float* C, int M, int K, int N, int act) {
    dim3 grid(cdiv(N, 64), cdiv(M, 128));
    gemm_kernel<<<grid, 256>>>(A, Wm, bias, C, M, K, N, act);
}

extern "C" void kernel_launch(void* const* d_in, const int* in_sizes, int n_in,
                              void* d_out, int out_size) {
    const float* x     = (const float*)d_in[0];
    const void*  edge  = d_in[1];
    const void*  batch = d_in[2];
    const float* Wl[9];
    const float* bl[9];
    for (int i = 0; i < 9; i++) {
        Wl[i] = (const float*)d_in[3 + 2 * i];
        bl[i] = (const float*)d_in[4 + 2 * i];
    }
    int n = in_sizes[2];         // number of nodes
    int E = in_sizes[1] / 2;     // number of edges

    float *bufA, *bufB, *bufC;
    cudaGetSymbolAddress((void**)&bufA, g_bufA);
    cudaGetSymbolAddress((void**)&bufB, g_bufB);
    cudaGetSymbolAddress((void**)&bufC, g_bufC);

    // --- graph normalization + CSR build (per launch; graph-capturable) ---
    detect_kernel<<<1, 1>>>(edge);
    init_cnt_kernel<<<cdiv(n, 256), 256>>>(n);
    count_kernel<<<cdiv(E, 256), 256>>>(edge, E);
    dinv_kernel<<<cdiv(n, 256), 256>>>(n);
    scan_kernel<<<1, 1024>>>(n);
    fill_edges_kernel<<<cdiv(E, 256), 256>>>(edge, E);
    fill_loops_kernel<<<cdiv(n, 256), 256>>>(n);

    // --- layers: A(XW)=(AX)W, aggregate at min(fan_in, fan_out) width ------
    static const int widths[10]  = {128, 128, 256, 384, 512, 512, 384, 256, 128, 32};
    static const int acts[9]     = {1, 1, 2, 1, 2, 2, 1, 1, 0};
    static const int aggfirst[9] = {1, 1, 1, 1, 1, 0, 0, 0, 0};

    const float* hin = x;
    float* hbufs[2] = {bufA, bufB};
    int pp = 0;
    for (int l = 0; l < 9; l++) {
        int K = widths[l], N = widths[l + 1];
        float* hout = hbufs[pp];
        if (aggfirst[l]) {
            spmm_launch(hin, bufC, K, nullptr, 0, n);
            gemm_launch(bufC, Wl[l], bl[l], hout, n, K, N, acts[l]);
        } else {
            gemm_launch(hin, Wl[l], nullptr, bufC, n, K, N, 0);
            spmm_launch(bufC, hout, N, bl[l], acts[l], n);
        }
        hin = hout;
        pp ^= 1;
    }

    // --- global mean pool ---------------------------------------------------
    zero_pool_kernel<<<cdiv(N_GRAPHS * 32, 256), 256>>>();
    pool_cnt_kernel<<<cdiv(n, 256), 256>>>(batch, n);
    pool_sum_kernel<<<cdiv(n * 32, 256), 256>>>(hin, batch, n);
    pool_fin_kernel<<<cdiv(N_GRAPHS * 32, 256), 256>>>((float*)d_out);
}

// round 3
// speedup vs baseline: 1.3047x; 1.3047x over previous
#include <cuda_runtime.h>
#include <cstdint>

#define N_MAX   50000
#define E_MAX   1700000
#define WMAX    512
#define N_GRAPHS 64

// ---------------- scratch (device globals) ----------------------------------
__device__ float g_bufA[(size_t)N_MAX * WMAX];
__device__ float g_bufB[(size_t)N_MAX * WMAX];
__device__ float g_bufC[(size_t)N_MAX * WMAX];
__device__ float g_wt[(size_t)WMAX * WMAX];      // transposed weight [N][K]
__device__ float g_dinv[N_MAX];
__device__ int   g_cnt[N_MAX];
__device__ int   g_rowptr[N_MAX + 1];
__device__ int   g_cur[N_MAX];
__device__ int   g_col[E_MAX];
__device__ float g_wgt[E_MAX];
__device__ float g_pool[N_GRAPHS * 32];
__device__ int   g_pcnt[N_GRAPHS];
__device__ int   g_is64;

// ---------------- index helpers ----------------------------------------------
__device__ __forceinline__ int ld_idx(const void* p, long i) {
    if (g_is64) return (int)((const long long*)p)[i];
    return ((const int*)p)[i];
}
__global__ void detect_kernel(const void* edge) {
    const int* p = (const int*)edge;
    bool is64 = true;
    for (int i = 0; i < 8; i++)
        if (p[2 * i + 1] != 0) is64 = false;
    g_is64 = is64 ? 1 : 0;
}

// ---------------- CSR build ---------------------------------------------------
__global__ void init_cnt_kernel(int n) {
    int i = blockIdx.x * blockDim.x + threadIdx.x;
    if (i < n) g_cnt[i] = 1;
}
__global__ void count_kernel(const void* edge, int E) {
    int e = blockIdx.x * blockDim.x + threadIdx.x;
    if (e < E) atomicAdd(&g_cnt[ld_idx(edge, (long)E + e)], 1);
}
__global__ void dinv_kernel(int n) {
    int i = blockIdx.x * blockDim.x + threadIdx.x;
    if (i < n) g_dinv[i] = rsqrtf((float)g_cnt[i]);
}
__global__ void scan_kernel(int n) {
    __shared__ int sh[1024];
    __shared__ int carry_s;
    int tid = threadIdx.x;
    if (tid == 0) carry_s = 0;
    __syncthreads();
    for (int base = 0; base < n; base += 1024) {
        int i = base + tid;
        int v = (i < n) ? g_cnt[i] : 0;
        sh[tid] = v;
        __syncthreads();
        for (int off = 1; off < 1024; off <<= 1) {
            int t = (tid >= off) ? sh[tid - off] : 0;
            __syncthreads();
            sh[tid] += t;
            __syncthreads();
        }
        int carry = carry_s;
        if (i < n) {
            int excl = carry + sh[tid] - v;
            g_rowptr[i] = excl;
            g_cur[i] = excl;
        }
        __syncthreads();
        if (tid == 1023) carry_s = carry + sh[1023];
        __syncthreads();
    }
    if (tid == 0) g_rowptr[n] = carry_s;
}
__global__ void fill_edges_kernel(const void* edge, int E) {
    int e = blockIdx.x * blockDim.x + threadIdx.x;
    if (e < E) {
        int src = ld_idx(edge, e);
        int dst = ld_idx(edge, (long)E + e);
        int pos = atomicAdd(&g_cur[dst], 1);
        g_col[pos] = src;
        g_wgt[pos] = g_dinv[src] * g_dinv[dst];
    }
}
__global__ void fill_loops_kernel(int n) {
    int i = blockIdx.x * blockDim.x + threadIdx.x;
    if (i < n) {
        int pos = atomicAdd(&g_cur[i], 1);
        g_col[pos] = i;
        g_wgt[pos] = g_dinv[i] * g_dinv[i];
    }
}

// ---------------- SpMM --------------------------------------------------------
template <int NR, int BD>
__global__ void spmm_kernel(const float* __restrict__ in, float* __restrict__ out,
                            const float* __restrict__ bias, int act) {
    constexpr int W = NR * BD;
    int node = blockIdx.x;
    int tid = threadIdx.x;
    int s = g_rowptr[node];
    int e = g_rowptr[node + 1];
    float acc[NR];
#pragma unroll
    for (int r = 0; r < NR; r++) acc[r] = 0.f;
    int p = s;
    for (; p + 1 < e; p += 2) {
        int c0 = g_col[p], c1 = g_col[p + 1];
        float w0 = g_wgt[p], w1 = g_wgt[p + 1];
        const float* r0 = in + (size_t)c0 * W;
        const float* r1 = in + (size_t)c1 * W;
#pragma unroll
        for (int r = 0; r < NR; r++)
            acc[r] += w0 * r0[tid + r * BD] + w1 * r1[tid + r * BD];
    }
    if (p < e) {
        int c0 = g_col[p];
        float w0 = g_wgt[p];
        const float* r0 = in + (size_t)c0 * W;
#pragma unroll
        for (int r = 0; r < NR; r++) acc[r] += w0 * r0[tid + r * BD];
    }
#pragma unroll
    for (int r = 0; r < NR; r++) {
        int col = tid + r * BD;
        float v = acc[r];
        if (bias) v += bias[col];
        if (act == 1) v = fmaxf(v, 0.f);
        else if (act == 2) v = (v > 0.f) ? v : 0.01f * v;
        out[(size_t)node * W + col] = v;
    }
}

// ---------------- weight transpose: Wt[n][k] = W[k][n] ------------------------
__global__ void transpose_kernel(const float* __restrict__ W, float* __restrict__ Wt,
                                 int K, int N) {
    __shared__ float t[32][33];
    int k0 = blockIdx.x * 32, n0 = blockIdx.y * 32;
    int x = threadIdx.x, y = threadIdx.y;
    for (int i = y; i < 32; i += 8) {
        int k = k0 + i, nn = n0 + x;
        t[i][x] = (k < K && nn < N) ? W[(size_t)k * N + nn] : 0.f;
    }
    __syncthreads();
    for (int i = y; i < 32; i += 8) {
        int nn = n0 + i, k = k0 + x;
        if (nn < N && k < K) Wt[(size_t)nn * K + k] = t[x][i];
    }
}

// ---------------- TF32 mma.sync GEMM (3xTF32 for fp32 accuracy) ---------------
// C[M,N] = A[M,K] * Wt[N,K]^T.  BM=128, BN=128, BK=32, 256 thr, 8 warps (2x4).
#define SA 36     // smem row stride (floats) — (4g+tg)%32 distinct => no conflicts

__device__ __forceinline__ void split_tf32(float x, uint32_t& hi, uint32_t& lo) {
    asm("cvt.rna.tf32.f32 %0, %1;" : "=r"(hi) : "f"(x));
    float l = x - __uint_as_float(hi);
    asm("cvt.rna.tf32.f32 %0, %1;" : "=r"(lo) : "f"(l));
}
__device__ __forceinline__ void mma8(float* d, const uint32_t* a, const uint32_t* b) {
    asm volatile(
        "mma.sync.aligned.m16n8k8.row.col.f32.tf32.tf32.f32 "
        "{%0,%1,%2,%3}, {%4,%5,%6,%7}, {%8,%9}, {%0,%1,%2,%3};"
        : "+f"(d[0]), "+f"(d[1]), "+f"(d[2]), "+f"(d[3])
        : "r"(a[0]), "r"(a[1]), "r"(a[2]), "r"(a[3]), "r"(b[0]), "r"(b[1]));
}

__global__ __launch_bounds__(256) void gemm_mma_kernel(
    const float* __restrict__ A, const float* __restrict__ Wt,
    const float* __restrict__ bias, float* __restrict__ C,
    int M, int K, int Nfull, int act)
{
    __shared__ float As[128 * SA];
    __shared__ float Bs[128 * SA];
    int tid = threadIdx.x;
    int wid = tid >> 5, lid = tid & 31;
    int wm = wid >> 2;          // 0..1 -> 64-row slab
    int wn = wid & 3;           // 0..3 -> 32-col slab
    int g  = lid >> 2;          // group 0..7
    int tg = lid & 3;           // thread-in-group
    int m0 = blockIdx.y * 128;
    int n0 = blockIdx.x * 128;

    float acc[4][4][4];
#pragma unroll
    for (int mi = 0; mi < 4; mi++)
#pragma unroll
        for (int ni = 0; ni < 4; ni++)
#pragma unroll
            for (int q = 0; q < 4; q++) acc[mi][ni][q] = 0.f;

    int KT = K >> 5;

    // initial tile load
    {
#pragma unroll
        for (int q = 0; q < 4; q++) {
            int idx = tid + q * 256;
            int r = idx >> 3, c4 = idx & 7;
            float4 v = make_float4(0.f, 0.f, 0.f, 0.f);
            if (m0 + r < M) v = *(const float4*)(A + (size_t)(m0 + r) * K + c4 * 4);
            *(float4*)&As[r * SA + c4 * 4] = v;
        }
#pragma unroll
        for (int q = 0; q < 4; q++) {
            int idx = tid + q * 256;
            int r = idx >> 3, c4 = idx & 7;
            float4 v = make_float4(0.f, 0.f, 0.f, 0.f);
            if (n0 + r < Nfull) v = *(const float4*)(Wt + (size_t)(n0 + r) * K + c4 * 4);
            *(float4*)&Bs[r * SA + c4 * 4] = v;
        }
    }
    __syncthreads();

    for (int kt = 0; kt < KT; kt++) {
        bool more = (kt + 1 < KT);
        float4 pa[4], pb[4];
        if (more) {
            int k0 = (kt + 1) << 5;
#pragma unroll
            for (int q = 0; q < 4; q++) {
                int idx = tid + q * 256;
                int r = idx >> 3, c4 = idx & 7;
                pa[q] = make_float4(0.f, 0.f, 0.f, 0.f);
                if (m0 + r < M) pa[q] = *(const float4*)(A + (size_t)(m0 + r) * K + k0 + c4 * 4);
                pb[q] = make_float4(0.f, 0.f, 0.f, 0.f);
                if (n0 + r < Nfull) pb[q] = *(const float4*)(Wt + (size_t)(n0 + r) * K + k0 + c4 * 4);
            }
        }

        // compute: 4 k-steps of 8
#pragma unroll
        for (int kk = 0; kk < 4; kk++) {
            int kb = kk * 8;
            uint32_t ah[4][4], al[4][4], bh[4][2], bl[4][2];
#pragma unroll
            for (int mi = 0; mi < 4; mi++) {
                int rb = wm * 64 + mi * 16;
                float a0 = As[(rb + g) * SA + kb + tg];
                float a1 = As[(rb + g + 8) * SA + kb + tg];
                float a2 = As[(rb + g) * SA + kb + tg + 4];
                float a3 = As[(rb + g + 8) * SA + kb + tg + 4];
                split_tf32(a0, ah[mi][0], al[mi][0]);
                split_tf32(a1, ah[mi][1], al[mi][1]);
                split_tf32(a2, ah[mi][2], al[mi][2]);
                split_tf32(a3, ah[mi][3], al[mi][3]);
            }
#pragma unroll
            for (int ni = 0; ni < 4; ni++) {
                int nb = wn * 32 + ni * 8;
                float b0 = Bs[(nb + g) * SA + kb + tg];
                float b1 = Bs[(nb + g) * SA + kb + tg + 4];
                split_tf32(b0, bh[ni][0], bl[ni][0]);
                split_tf32(b1, bh[ni][1], bl[ni][1]);
            }
#pragma unroll
            for (int mi = 0; mi < 4; mi++)
#pragma unroll
                for (int ni = 0; ni < 4; ni++) {
                    mma8(acc[mi][ni], ah[mi], bh[ni]);
                    mma8(acc[mi][ni], ah[mi], bl[ni]);
                    mma8(acc[mi][ni], al[mi], bh[ni]);
                }
        }

        if (more) {
            __syncthreads();
#pragma unroll
            for (int q = 0; q < 4; q++) {
                int idx = tid + q * 256;
                int r = idx >> 3, c4 = idx & 7;
                *(float4*)&As[r * SA + c4 * 4] = pa[q];
                *(float4*)&Bs[r * SA + c4 * 4] = pb[q];
            }
            __syncthreads();
        }
    }

    // epilogue: bias + activation, float2 stores
#pragma unroll
    for (int mi = 0; mi < 4; mi++) {
        int row0 = m0 + wm * 64 + mi * 16 + g;
        int row1 = row0 + 8;
#pragma unroll
        for (int ni = 0; ni < 4; ni++) {
            int col = n0 + wn * 32 + ni * 8 + 2 * tg;
            if (col >= Nfull) continue;
            float bx = 0.f, by = 0.f;
            if (bias) { bx = bias[col]; by = bias[col + 1]; }
#pragma unroll
            for (int h = 0; h < 2; h++) {
                int row = h ? row1 : row0;
                if (row >= M) continue;
                float vx = acc[mi][ni][h * 2 + 0] + bx;
                float vy = acc[mi][ni][h * 2 + 1] + by;
                if (act == 1) { vx = fmaxf(vx, 0.f); vy = fmaxf(vy, 0.f); }
                else if (act == 2) {
                    vx = vx > 0.f ? vx : 0.01f * vx;
                    vy = vy > 0.f ? vy : 0.01f * vy;
                }
                *(float2*)(C + (size_t)row * Nfull + col) = make_float2(vx, vy);
            }
        }
    }
}

// ---------------- mean pool ---------------------------------------------------
__global__ void zero_pool_kernel() {
    int i = blockIdx.x * blockDim.x + threadIdx.x;
    if (i < N_GRAPHS * 32) g_pool[i] = 0.f;
    if (i < N_GRAPHS) g_pcnt[i] = 0;
}
__global__ void pool_cnt_kernel(const void* batch, int n) {
    int i = blockIdx.x * blockDim.x + threadIdx.x;
    if (i < n) atomicAdd(&g_pcnt[ld_idx(batch, i)], 1);
}
__global__ void pool_sum_kernel(const float* __restrict__ h, const void* batch, int n) {
    int idx = blockIdx.x * blockDim.x + threadIdx.x;
    if (idx < n * 32) {
        int node = idx >> 5;
        int c = idx & 31;
        int b = ld_idx(batch, node);
        atomicAdd(&g_pool[b * 32 + c], h[(size_t)node * 32 + c]);
    }
}
__global__ void pool_fin_kernel(float* out) {
    int i = blockIdx.x * blockDim.x + threadIdx.x;
    if (i < N_GRAPHS * 32) {
        int b = i >> 5;
        out[i] = g_pool[i] / fmaxf((float)g_pcnt[b], 1.0f);
    }
}

// ---------------- host driver --------------------------------------------------
static inline int cdiv(int a, int b) { return (a + b - 1) / b; }

static void spmm_launch(const float* in, float* out, int W,
                        const float* bias, int act, int n) {
    if (W == 32)       spmm_kernel<1, 32><<<n, 32>>>(in, out, bias, act);
    else if (W == 128) spmm_kernel<1, 128><<<n, 128>>>(in, out, bias, act);
    else if (W == 256) spmm_kernel<2, 128><<<n, 128>>>(in, out, bias, act);
    else if (W == 384) spmm_kernel<3, 128><<<n, 128>>>(in, out, bias, act);
    else               spmm_kernel<4, 128><<<n, 128>>>(in, out, bias, act);
}

static void gemm_launch(const float* Ain, const float* Wm, float* wt,
                        const float* bias, float* C, int M, int K, int N, int act) {
    transpose_kernel<<<dim3(cdiv(K, 32), cdiv(N, 32)), dim3(32, 8)>>>(Wm, wt, K, N);
    dim3 grid(cdiv(N, 128), cdiv(M, 128));
    gemm_mma_kernel<<<grid, 256>>>(Ain, wt, bias, C, M, K, N, act);
}

extern "C" void kernel_launch(void* const* d_in, const int* in_sizes, int n_in,
                              void* d_out, int out_size) {
    const float* x     = (const float*)d_in[0];
    const void*  edge  = d_in[1];
    const void*  batch = d_in[2];
    const float* Wl[9];
    const float* bl[9];
    for (int i = 0; i < 9; i++) {
        Wl[i] = (const float*)d_in[3 + 2 * i];
        bl[i] = (const float*)d_in[4 + 2 * i];
    }
    int n = in_sizes[2];
    int E = in_sizes[1] / 2;

    float *bufA, *bufB, *bufC, *wt;
    cudaGetSymbolAddress((void**)&bufA, g_bufA);
    cudaGetSymbolAddress((void**)&bufB, g_bufB);
    cudaGetSymbolAddress((void**)&bufC, g_bufC);
    cudaGetSymbolAddress((void**)&wt, g_wt);

    // --- CSR build ---
    detect_kernel<<<1, 1>>>(edge);
    init_cnt_kernel<<<cdiv(n, 256), 256>>>(n);
    count_kernel<<<cdiv(E, 256), 256>>>(edge, E);
    dinv_kernel<<<cdiv(n, 256), 256>>>(n);
    scan_kernel<<<1, 1024>>>(n);
    fill_edges_kernel<<<cdiv(E, 256), 256>>>(edge, E);
    fill_loops_kernel<<<cdiv(n, 256), 256>>>(n);

    // --- layers: A(XW)=(AX)W, aggregate at min(fan_in, fan_out) width ------
    static const int widths[10]  = {128, 128, 256, 384, 512, 512, 384, 256, 128, 32};
    static const int acts[9]     = {1, 1, 2, 1, 2, 2, 1, 1, 0};
    static const int aggfirst[9] = {1, 1, 1, 1, 1, 0, 0, 0, 0};

    const float* hin = x;
    float* hbufs[2] = {bufA, bufB};
    int pp = 0;
    for (int l = 0; l < 9; l++) {
        int K = widths[l], N = widths[l + 1];
        float* hout = hbufs[pp];
        if (aggfirst[l]) {
            spmm_launch(hin, bufC, K, nullptr, 0, n);
            gemm_launch(bufC, Wl[l], wt, bl[l], hout, n, K, N, acts[l]);
        } else {
            gemm_launch(hin, Wl[l], wt, nullptr, bufC, n, K, N, 0);
            spmm_launch(bufC, hout, N, bl[l], acts[l], n);
        }
        hin = hout;
        pp ^= 1;
    }

    // --- pool ---
    zero_pool_kernel<<<cdiv(N_GRAPHS * 32, 256), 256>>>();
    pool_cnt_kernel<<<cdiv(n, 256), 256>>>(batch, n);
    pool_sum_kernel<<<cdiv(n * 32, 256), 256>>>(hin, batch, n);
    pool_fin_kernel<<<cdiv(N_GRAPHS * 32, 256), 256>>>((float*)d_out);
}

// round 4
// speedup vs baseline: 1.5529x; 1.1903x over previous
#include <cuda_runtime.h>
#include <cstdint>

#define N_MAX   50000
#define E_MAX   1700000
#define WMAX    512
#define N_GRAPHS 64

// ---------------- scratch (device globals) ----------------------------------
__device__ float g_bufA[(size_t)N_MAX * WMAX];
__device__ float g_bufB[(size_t)N_MAX * WMAX];
__device__ float g_bufC[(size_t)N_MAX * WMAX];
__device__ float g_wt9[(size_t)9 * WMAX * WMAX];   // all transposed weights [N][K]
__device__ float g_dinv[N_MAX];
__device__ int   g_cnt[N_MAX];
__device__ int   g_rowptr[N_MAX + 1];
__device__ int   g_cur[N_MAX];
__device__ int   g_col[E_MAX];
__device__ float g_wgt[E_MAX];
__device__ float g_pool[N_GRAPHS * 32];
__device__ int   g_pcnt[N_GRAPHS];
__device__ int   g_is64;

__device__ const int d_widths[10] = {128, 128, 256, 384, 512, 512, 384, 256, 128, 32};

// ---------------- helpers -----------------------------------------------------
__device__ __forceinline__ uint32_t smem_u32(const void* p) {
    uint32_t a;
    asm("{ .reg .u64 t; cvta.to.shared.u64 t, %1; cvt.u32.u64 %0, t; }" : "=r"(a) : "l"(p));
    return a;
}
__device__ __forceinline__ int ld_idx(const void* p, long i) {
    if (g_is64) return (int)((const long long*)p)[i];
    return ((const int*)p)[i];
}
__global__ void detect_kernel(const void* edge) {
    const int* p = (const int*)edge;
    bool is64 = true;
    for (int i = 0; i < 8; i++)
        if (p[2 * i + 1] != 0) is64 = false;
    g_is64 = is64 ? 1 : 0;
}

// ---------------- CSR build ---------------------------------------------------
__global__ void init_cnt_kernel(int n) {
    int i = blockIdx.x * blockDim.x + threadIdx.x;
    if (i < n) g_cnt[i] = 1;
}
__global__ void count_kernel(const void* edge, int E) {
    int e = blockIdx.x * blockDim.x + threadIdx.x;
    if (e < E) atomicAdd(&g_cnt[ld_idx(edge, (long)E + e)], 1);
}
__global__ void dinv_kernel(int n) {
    int i = blockIdx.x * blockDim.x + threadIdx.x;
    if (i < n) g_dinv[i] = rsqrtf((float)g_cnt[i]);
}
__global__ void scan_kernel(int n) {
    __shared__ int sh[1024];
    __shared__ int carry_s;
    int tid = threadIdx.x;
    if (tid == 0) carry_s = 0;
    __syncthreads();
    for (int base = 0; base < n; base += 1024) {
        int i = base + tid;
        int v = (i < n) ? g_cnt[i] : 0;
        sh[tid] = v;
        __syncthreads();
        for (int off = 1; off < 1024; off <<= 1) {
            int t = (tid >= off) ? sh[tid - off] : 0;
            __syncthreads();
            sh[tid] += t;
            __syncthreads();
        }
        int carry = carry_s;
        if (i < n) {
            int excl = carry + sh[tid] - v;
            g_rowptr[i] = excl;
            g_cur[i] = excl;
        }
        __syncthreads();
        if (tid == 1023) carry_s = carry + sh[1023];
        __syncthreads();
    }
    if (tid == 0) g_rowptr[n] = carry_s;
}
__global__ void fill_edges_kernel(const void* edge, int E) {
    int e = blockIdx.x * blockDim.x + threadIdx.x;
    if (e < E) {
        int src = ld_idx(edge, e);
        int dst = ld_idx(edge, (long)E + e);
        int pos = atomicAdd(&g_cur[dst], 1);
        g_col[pos] = src;
        g_wgt[pos] = g_dinv[src] * g_dinv[dst];
    }
}
__global__ void fill_loops_kernel(int n) {
    int i = blockIdx.x * blockDim.x + threadIdx.x;
    if (i < n) {
        int pos = atomicAdd(&g_cur[i], 1);
        g_col[pos] = i;
        g_wgt[pos] = g_dinv[i] * g_dinv[i];
    }
}

// ---------------- SpMM (float4, 4-edge unroll) --------------------------------
__global__ void spmm4_kernel(const float4* __restrict__ in, float4* __restrict__ out,
                             const float4* __restrict__ bias, int act) {
    int node = blockIdx.x;
    int W4 = blockDim.x;
    int t = threadIdx.x;
    int s = g_rowptr[node], e = g_rowptr[node + 1];
    float4 acc = make_float4(0.f, 0.f, 0.f, 0.f);
    int p = s;
    for (; p + 3 < e; p += 4) {
        int c0 = g_col[p], c1 = g_col[p + 1], c2 = g_col[p + 2], c3 = g_col[p + 3];
        float w0 = g_wgt[p], w1 = g_wgt[p + 1], w2 = g_wgt[p + 2], w3 = g_wgt[p + 3];
        float4 v0 = in[(size_t)c0 * W4 + t];
        float4 v1 = in[(size_t)c1 * W4 + t];
        float4 v2 = in[(size_t)c2 * W4 + t];
        float4 v3 = in[(size_t)c3 * W4 + t];
        acc.x += w0 * v0.x + w1 * v1.x + w2 * v2.x + w3 * v3.x;
        acc.y += w0 * v0.y + w1 * v1.y + w2 * v2.y + w3 * v3.y;
        acc.z += w0 * v0.z + w1 * v1.z + w2 * v2.z + w3 * v3.z;
        acc.w += w0 * v0.w + w1 * v1.w + w2 * v2.w + w3 * v3.w;
    }
    for (; p < e; p++) {
        int c0 = g_col[p];
        float w0 = g_wgt[p];
        float4 v0 = in[(size_t)c0 * W4 + t];
        acc.x += w0 * v0.x; acc.y += w0 * v0.y;
        acc.z += w0 * v0.z; acc.w += w0 * v0.w;
    }
    if (bias) {
        float4 b = bias[t];
        acc.x += b.x; acc.y += b.y; acc.z += b.z; acc.w += b.w;
    }
    if (act == 1) {
        acc.x = fmaxf(acc.x, 0.f); acc.y = fmaxf(acc.y, 0.f);
        acc.z = fmaxf(acc.z, 0.f); acc.w = fmaxf(acc.w, 0.f);
    } else if (act == 2) {
        acc.x = acc.x > 0.f ? acc.x : 0.01f * acc.x;
        acc.y = acc.y > 0.f ? acc.y : 0.01f * acc.y;
        acc.z = acc.z > 0.f ? acc.z : 0.01f * acc.z;
        acc.w = acc.w > 0.f ? acc.w : 0.01f * acc.w;
    }
    out[(size_t)node * W4 + t] = acc;
}

// scalar fallback for W=32
__global__ void spmm_kernel32(const float* __restrict__ in, float* __restrict__ out,
                              const float* __restrict__ bias, int act) {
    int node = blockIdx.x;
    int tid = threadIdx.x;
    int s = g_rowptr[node], e = g_rowptr[node + 1];
    float acc = 0.f;
    int p = s;
    for (; p + 1 < e; p += 2) {
        int c0 = g_col[p], c1 = g_col[p + 1];
        float w0 = g_wgt[p], w1 = g_wgt[p + 1];
        acc += w0 * in[(size_t)c0 * 32 + tid] + w1 * in[(size_t)c1 * 32 + tid];
    }
    if (p < e) acc += g_wgt[p] * in[(size_t)g_col[p] * 32 + tid];
    float v = acc;
    if (bias) v += bias[tid];
    if (act == 1) v = fmaxf(v, 0.f);
    else if (act == 2) v = (v > 0.f) ? v : 0.01f * v;
    out[(size_t)node * 32 + tid] = v;
}

// ---------------- fused weight transpose (all 9 layers) -----------------------
struct TParams { const float* W[9]; };
__global__ void transpose_all_kernel(TParams tp, float* wt9) {
    int l = blockIdx.z;
    int K = d_widths[l], N = d_widths[l + 1];
    int k0 = blockIdx.x * 32, n0 = blockIdx.y * 32;
    if (k0 >= K || n0 >= N) return;
    const float* W = tp.W[l];
    float* Wt = wt9 + (size_t)l * WMAX * WMAX;
    __shared__ float t[32][33];
    int x = threadIdx.x, y = threadIdx.y;
    for (int i = y; i < 32; i += 8) {
        int k = k0 + i, nn = n0 + x;
        t[i][x] = (k < K && nn < N) ? W[(size_t)k * N + nn] : 0.f;
    }
    __syncthreads();
    for (int i = y; i < 32; i += 8) {
        int nn = n0 + i, k = k0 + x;
        if (nn < N && k < K) Wt[(size_t)nn * K + k] = t[x][i];
    }
}

// ---------------- TF32 mma.sync GEMM (3xTF32), cp.async pipelined -------------
// C[M,N] = A[M,K] * Wt[N,K]^T.  BM=128, BN=128, BK=32, 256 thr, 8 warps (2x4).
#define SA 36
#define TILE_FLOATS (128 * SA)             // 4608 floats per operand tile
#define BUF_FLOATS  (2 * TILE_FLOATS)      // A tile + B tile
#define GEMM_SMEM_BYTES (2 * BUF_FLOATS * 4)   // double buffered: 73728 B

__device__ __forceinline__ void split_tf32(float x, uint32_t& hi, uint32_t& lo) {
    asm("cvt.rna.tf32.f32 %0, %1;" : "=r"(hi) : "f"(x));
    float l = x - __uint_as_float(hi);
    asm("cvt.rna.tf32.f32 %0, %1;" : "=r"(lo) : "f"(l));
}
__device__ __forceinline__ void mma8(float* d, const uint32_t* a, const uint32_t* b) {
    asm volatile(
        "mma.sync.aligned.m16n8k8.row.col.f32.tf32.tf32.f32 "
        "{%0,%1,%2,%3}, {%4,%5,%6,%7}, {%8,%9}, {%0,%1,%2,%3};"
        : "+f"(d[0]), "+f"(d[1]), "+f"(d[2]), "+f"(d[3])
        : "r"(a[0]), "r"(a[1]), "r"(a[2]), "r"(a[3]), "r"(b[0]), "r"(b[1]));
}
__device__ __forceinline__ void cp_async16(uint32_t dst, const float* src, int sz) {
    asm volatile("cp.async.ca.shared.global [%0], [%1], 16, %2;"
                 :: "r"(dst), "l"(src), "r"(sz) : "memory");
}

__global__ __launch_bounds__(256) void gemm_mma_kernel(
    const float* __restrict__ A, const float* __restrict__ Wt,
    const float* __restrict__ bias, float* __restrict__ C,
    int M, int K, int Nfull, int act)
{
    extern __shared__ float smem[];
    uint32_t sb = smem_u32(smem);
    int tid = threadIdx.x;
    int wid = tid >> 5, lid = tid & 31;
    int wm = wid >> 2;
    int wn = wid & 3;
    int g  = lid >> 2;
    int tg = lid & 3;
    int m0 = blockIdx.y * 128;
    int n0 = blockIdx.x * 128;

    float acc[4][4][4];
#pragma unroll
    for (int mi = 0; mi < 4; mi++)
#pragma unroll
        for (int ni = 0; ni < 4; ni++)
#pragma unroll
            for (int q = 0; q < 4; q++) acc[mi][ni][q] = 0.f;

    int KT = K >> 5;

    auto load_tile = [&](int kt, int b) {
        int k0 = kt << 5;
        uint32_t base = sb + (uint32_t)(b * BUF_FLOATS) * 4u;
#pragma unroll
        for (int q = 0; q < 4; q++) {
            int idx = tid + q * 256;
            int r = idx >> 3, c4 = idx & 7;
            const float* src = A + (size_t)(m0 + r) * K + k0 + c4 * 4;
            cp_async16(base + (uint32_t)(r * SA + c4 * 4) * 4u, src, (m0 + r < M) ? 16 : 0);
        }
        uint32_t baseB = base + (uint32_t)TILE_FLOATS * 4u;
#pragma unroll
        for (int q = 0; q < 4; q++) {
            int idx = tid + q * 256;
            int r = idx >> 3, c4 = idx & 7;
            const float* src = Wt + (size_t)(n0 + r) * K + k0 + c4 * 4;
            cp_async16(baseB + (uint32_t)(r * SA + c4 * 4) * 4u, src, (n0 + r < Nfull) ? 16 : 0);
        }
    };

    load_tile(0, 0);
    asm volatile("cp.async.commit_group;" ::: "memory");
    if (KT > 1) load_tile(1, 1);
    asm volatile("cp.async.commit_group;" ::: "memory");

    for (int kt = 0; kt < KT; kt++) {
        asm volatile("cp.async.wait_group 1;" ::: "memory");
        __syncthreads();
        const float* As = smem + (kt & 1) * BUF_FLOATS;
        const float* Bs = As + TILE_FLOATS;

#pragma unroll
        for (int kk = 0; kk < 4; kk++) {
            int kb = kk * 8;
            uint32_t ah[4][4], al[4][4], bh[4][2], bl[4][2];
#pragma unroll
            for (int mi = 0; mi < 4; mi++) {
                int rb = wm * 64 + mi * 16;
                float a0 = As[(rb + g) * SA + kb + tg];
                float a1 = As[(rb + g + 8) * SA + kb + tg];
                float a2 = As[(rb + g) * SA + kb + tg + 4];
                float a3 = As[(rb + g + 8) * SA + kb + tg + 4];
                split_tf32(a0, ah[mi][0], al[mi][0]);
                split_tf32(a1, ah[mi][1], al[mi][1]);
                split_tf32(a2, ah[mi][2], al[mi][2]);
                split_tf32(a3, ah[mi][3], al[mi][3]);
            }
#pragma unroll
            for (int ni = 0; ni < 4; ni++) {
                int nb = wn * 32 + ni * 8;
                float b0 = Bs[(nb + g) * SA + kb + tg];
                float b1 = Bs[(nb + g) * SA + kb + tg + 4];
                split_tf32(b0, bh[ni][0], bl[ni][0]);
                split_tf32(b1, bh[ni][1], bl[ni][1]);
            }
#pragma unroll
            for (int mi = 0; mi < 4; mi++)
#pragma unroll
                for (int ni = 0; ni < 4; ni++) {
                    mma8(acc[mi][ni], ah[mi], bh[ni]);
                    mma8(acc[mi][ni], ah[mi], bl[ni]);
                    mma8(acc[mi][ni], al[mi], bh[ni]);
                }
        }
        __syncthreads();
        if (kt + 2 < KT) load_tile(kt + 2, kt & 1);
        asm volatile("cp.async.commit_group;" ::: "memory");
    }

    // epilogue: bias + activation, float2 stores
#pragma unroll
    for (int mi = 0; mi < 4; mi++) {
        int row0 = m0 + wm * 64 + mi * 16 + g;
        int row1 = row0 + 8;
#pragma unroll
        for (int ni = 0; ni < 4; ni++) {
            int col = n0 + wn * 32 + ni * 8 + 2 * tg;
            if (col >= Nfull) continue;
            float bx = 0.f, by = 0.f;
            if (bias) { bx = bias[col]; by = bias[col + 1]; }
#pragma unroll
            for (int h = 0; h < 2; h++) {
                int row = h ? row1 : row0;
                if (row >= M) continue;
                float vx = acc[mi][ni][h * 2 + 0] + bx;
                float vy = acc[mi][ni][h * 2 + 1] + by;
                if (act == 1) { vx = fmaxf(vx, 0.f); vy = fmaxf(vy, 0.f); }
                else if (act == 2) {
                    vx = vx > 0.f ? vx : 0.01f * vx;
                    vy = vy > 0.f ? vy : 0.01f * vy;
                }
                *(float2*)(C + (size_t)row * Nfull + col) = make_float2(vx, vy);
            }
        }
    }
}

// ---------------- mean pool ---------------------------------------------------
__global__ void zero_pool_kernel() {
    int i = blockIdx.x * blockDim.x + threadIdx.x;
    if (i < N_GRAPHS * 32) g_pool[i] = 0.f;
    if (i < N_GRAPHS) g_pcnt[i] = 0;
}
__global__ void pool_cnt_kernel(const void* batch, int n) {
    int i = blockIdx.x * blockDim.x + threadIdx.x;
    if (i < n) atomicAdd(&g_pcnt[ld_idx(batch, i)], 1);
}
__global__ void pool_sum_kernel(const float* __restrict__ h, const void* batch, int n) {
    int idx = blockIdx.x * blockDim.x + threadIdx.x;
    if (idx < n * 32) {
        int node = idx >> 5;
        int c = idx & 31;
        int b = ld_idx(batch, node);
        atomicAdd(&g_pool[b * 32 + c], h[(size_t)node * 32 + c]);
    }
}
__global__ void pool_fin_kernel(float* out) {
    int i = blockIdx.x * blockDim.x + threadIdx.x;
    if (i < N_GRAPHS * 32) {
        int b = i >> 5;
        out[i] = g_pool[i] / fmaxf((float)g_pcnt[b], 1.0f);
    }
}

// ---------------- host driver --------------------------------------------------
static inline int cdiv(int a, int b) { return (a + b - 1) / b; }

static void spmm_launch(const float* in, float* out, int W,
                        const float* bias, int act, int n) {
    if (W == 32) {
        spmm_kernel32<<<n, 32>>>(in, out, bias, act);
    } else {
        spmm4_kernel<<<n, W / 4>>>((const float4*)in, (float4*)out,
                                   (const float4*)bias, act);
    }
}

extern "C" void kernel_launch(void* const* d_in, const int* in_sizes, int n_in,
                              void* d_out, int out_size) {
    const float* x     = (const float*)d_in[0];
    const void*  edge  = d_in[1];
    const void*  batch = d_in[2];
    TParams tp;
    const float* bl[9];
    for (int i = 0; i < 9; i++) {
        tp.W[i] = (const float*)d_in[3 + 2 * i];
        bl[i]   = (const float*)d_in[4 + 2 * i];
    }
    int n = in_sizes[2];
    int E = in_sizes[1] / 2;

    float *bufA, *bufB, *bufC, *wt9;
    cudaGetSymbolAddress((void**)&bufA, g_bufA);
    cudaGetSymbolAddress((void**)&bufB, g_bufB);
    cudaGetSymbolAddress((void**)&bufC, g_bufC);
    cudaGetSymbolAddress((void**)&wt9, g_wt9);

    cudaFuncSetAttribute(gemm_mma_kernel, cudaFuncAttributeMaxDynamicSharedMemorySize,
                         GEMM_SMEM_BYTES);

    // --- CSR build + weight transposes ---
    detect_kernel<<<1, 1>>>(edge);
    transpose_all_kernel<<<dim3(16, 16, 9), dim3(32, 8)>>>(tp, wt9);
    init_cnt_kernel<<<cdiv(n, 256), 256>>>(n);
    count_kernel<<<cdiv(E, 256), 256>>>(edge, E);
    dinv_kernel<<<cdiv(n, 256), 256>>>(n);
    scan_kernel<<<1, 1024>>>(n);
    fill_edges_kernel<<<cdiv(E, 256), 256>>>(edge, E);
    fill_loops_kernel<<<cdiv(n, 256), 256>>>(n);

    // --- layers: A(XW)=(AX)W, aggregate at min(fan_in, fan_out) width ------
    static const int widths[10]  = {128, 128, 256, 384, 512, 512, 384, 256, 128, 32};
    static const int acts[9]     = {1, 1, 2, 1, 2, 2, 1, 1, 0};
    static const int aggfirst[9] = {1, 1, 1, 1, 1, 0, 0, 0, 0};

    const float* hin = x;
    float* hbufs[2] = {bufA, bufB};
    int pp = 0;
    for (int l = 0; l < 9; l++) {
        int K = widths[l], N = widths[l + 1];
        float* hout = hbufs[pp];
        const float* wt_l = wt9 + (size_t)l * WMAX * WMAX;
        dim3 grid(cdiv(N, 128), cdiv(n, 128));
        if (aggfirst[l]) {
            spmm_launch(hin, bufC, K, nullptr, 0, n);
            gemm_mma_kernel<<<grid, 256, GEMM_SMEM_BYTES>>>(bufC, wt_l, bl[l], hout, n, K, N, acts[l]);
        } else {
            gemm_mma_kernel<<<grid, 256, GEMM_SMEM_BYTES>>>(hin, wt_l, nullptr, bufC, n, K, N, 0);
            spmm_launch(bufC, hout, N, bl[l], acts[l], n);
        }
        hin = hout;
        pp ^= 1;
    }

    // --- pool ---
    zero_pool_kernel<<<cdiv(N_GRAPHS * 32, 256), 256>>>();
    pool_cnt_kernel<<<cdiv(n, 256), 256>>>(batch, n);
    pool_sum_kernel<<<cdiv(n * 32, 256), 256>>>(hin, batch, n);
    pool_fin_kernel<<<cdiv(N_GRAPHS * 32, 256), 256>>>((float*)d_out);
}

// round 5
// speedup vs baseline: 2.1134x; 1.3609x over previous
#include <cuda_runtime.h>
#include <cstdint>

#define N_MAX   50000
#define E_MAX   1700000
#define WMAX    512
#define N_GRAPHS 64

// ---------------- scratch (device globals) ----------------------------------
__device__ float    g_F[(size_t)N_MAX * WMAX];                 // fp32 ping buffer
__device__ float    g_out32[(size_t)N_MAX * 32];               // final layer fp32
__device__ uint32_t g_hi1[(size_t)N_MAX * WMAX / 2];           // bf16 hi plane (pair 1)
__device__ uint32_t g_lo1[(size_t)N_MAX * WMAX / 2];
__device__ uint32_t g_hi2[(size_t)N_MAX * WMAX / 2];           // pair 2 (layer-4 gemm out)
__device__ uint32_t g_lo2[(size_t)N_MAX * WMAX / 2];
__device__ float    g_wt9[(size_t)9 * WMAX * WMAX];            // fp32 transposed weights
__device__ uint32_t g_whi[(size_t)9 * WMAX * WMAX / 2];        // weight bf16 planes
__device__ uint32_t g_wlo[(size_t)9 * WMAX * WMAX / 2];
__device__ float    g_dinv[N_MAX];
__device__ int      g_cnt[N_MAX];
__device__ int      g_rowptr[N_MAX + 1];
__device__ int      g_cur[N_MAX];
__device__ int      g_col[E_MAX];
__device__ float    g_wgt[E_MAX];
__device__ float    g_pool[N_GRAPHS * 32];
__device__ int      g_pcnt[N_GRAPHS];
__device__ int      g_is64;

__device__ const int d_widths[10] = {128, 128, 256, 384, 512, 512, 384, 256, 128, 32};

// ---------------- helpers -----------------------------------------------------
__device__ __forceinline__ uint32_t smem_u32(const void* p) {
    uint32_t a;
    asm("{ .reg .u64 t; cvta.to.shared.u64 t, %1; cvt.u32.u64 %0, t; }" : "=r"(a) : "l"(p));
    return a;
}
__device__ __forceinline__ int ld_idx(const void* p, long i) {
    if (g_is64) return (int)((const long long*)p)[i];
    return ((const int*)p)[i];
}
// split two consecutive floats into packed bf16x2 hi/lo words (low 16 = first elem)
__device__ __forceinline__ void split2(float x0, float x1, uint32_t& hi, uint32_t& lo) {
    uint32_t h;
    asm("cvt.rn.bf16x2.f32 %0, %1, %2;" : "=r"(h) : "f"(x1), "f"(x0));
    float h0 = __uint_as_float(h << 16);
    float h1 = __uint_as_float(h & 0xFFFF0000u);
    float r0 = x0 - h0, r1 = x1 - h1;
    asm("cvt.rn.bf16x2.f32 %0, %1, %2;" : "=r"(lo) : "f"(r1), "f"(r0));
    hi = h;
}
__global__ void detect_kernel(const void* edge) {
    const int* p = (const int*)edge;
    bool is64 = true;
    for (int i = 0; i < 8; i++)
        if (p[2 * i + 1] != 0) is64 = false;
    g_is64 = is64 ? 1 : 0;
}

// ---------------- CSR build ---------------------------------------------------
__global__ void init_cnt_kernel(int n) {
    int i = blockIdx.x * blockDim.x + threadIdx.x;
    if (i < n) g_cnt[i] = 1;
}
__global__ void count_kernel(const void* edge, int E) {
    int e = blockIdx.x * blockDim.x + threadIdx.x;
    if (e < E) atomicAdd(&g_cnt[ld_idx(edge, (long)E + e)], 1);
}
__global__ void dinv_kernel(int n) {
    int i = blockIdx.x * blockDim.x + threadIdx.x;
    if (i < n) g_dinv[i] = rsqrtf((float)g_cnt[i]);
}
__global__ void scan_kernel(int n) {
    __shared__ int sh[1024];
    __shared__ int carry_s;
    int tid = threadIdx.x;
    if (tid == 0) carry_s = 0;
    __syncthreads();
    for (int base = 0; base < n; base += 1024) {
        int i = base + tid;
        int v = (i < n) ? g_cnt[i] : 0;
        sh[tid] = v;
        __syncthreads();
        for (int off = 1; off < 1024; off <<= 1) {
            int t = (tid >= off) ? sh[tid - off] : 0;
            __syncthreads();
            sh[tid] += t;
            __syncthreads();
        }
        int carry = carry_s;
        if (i < n) {
            int excl = carry + sh[tid] - v;
            g_rowptr[i] = excl;
            g_cur[i] = excl;
        }
        __syncthreads();
        if (tid == 1023) carry_s = carry + sh[1023];
        __syncthreads();
    }
    if (tid == 0) g_rowptr[n] = carry_s;
}
__global__ void fill_edges_kernel(const void* edge, int E) {
    int e = blockIdx.x * blockDim.x + threadIdx.x;
    if (e < E) {
        int src = ld_idx(edge, e);
        int dst = ld_idx(edge, (long)E + e);
        int pos = atomicAdd(&g_cur[dst], 1);
        g_col[pos] = src;
        g_wgt[pos] = g_dinv[src] * g_dinv[dst];
    }
}
__global__ void fill_loops_kernel(int n) {
    int i = blockIdx.x * blockDim.x + threadIdx.x;
    if (i < n) {
        int pos = atomicAdd(&g_cur[i], 1);
        g_col[pos] = i;
        g_wgt[pos] = g_dinv[i] * g_dinv[i];
    }
}

// ---------------- SpMM (float4 gather, 4-edge unroll, split-bf16 output) ------
__global__ void spmm4_split_kernel(const float4* __restrict__ in,
                                   uint2* __restrict__ outHi, uint2* __restrict__ outLo,
                                   const float4* __restrict__ bias, int act) {
    int node = blockIdx.x;
    int W4 = blockDim.x;
    int t = threadIdx.x;
    int s = g_rowptr[node], e = g_rowptr[node + 1];
    float4 acc = make_float4(0.f, 0.f, 0.f, 0.f);
    int p = s;
    for (; p + 3 < e; p += 4) {
        int c0 = g_col[p], c1 = g_col[p + 1], c2 = g_col[p + 2], c3 = g_col[p + 3];
        float w0 = g_wgt[p], w1 = g_wgt[p + 1], w2 = g_wgt[p + 2], w3 = g_wgt[p + 3];
        float4 v0 = in[(size_t)c0 * W4 + t];
        float4 v1 = in[(size_t)c1 * W4 + t];
        float4 v2 = in[(size_t)c2 * W4 + t];
        float4 v3 = in[(size_t)c3 * W4 + t];
        acc.x += w0 * v0.x + w1 * v1.x + w2 * v2.x + w3 * v3.x;
        acc.y += w0 * v0.y + w1 * v1.y + w2 * v2.y + w3 * v3.y;
        acc.z += w0 * v0.z + w1 * v1.z + w2 * v2.z + w3 * v3.z;
        acc.w += w0 * v0.w + w1 * v1.w + w2 * v2.w + w3 * v3.w;
    }
    for (; p < e; p++) {
        int c0 = g_col[p];
        float w0 = g_wgt[p];
        float4 v0 = in[(size_t)c0 * W4 + t];
        acc.x += w0 * v0.x; acc.y += w0 * v0.y;
        acc.z += w0 * v0.z; acc.w += w0 * v0.w;
    }
    if (bias) {
        float4 b = bias[t];
        acc.x += b.x; acc.y += b.y; acc.z += b.z; acc.w += b.w;
    }
    if (act == 1) {
        acc.x = fmaxf(acc.x, 0.f); acc.y = fmaxf(acc.y, 0.f);
        acc.z = fmaxf(acc.z, 0.f); acc.w = fmaxf(acc.w, 0.f);
    } else if (act == 2) {
        acc.x = acc.x > 0.f ? acc.x : 0.01f * acc.x;
        acc.y = acc.y > 0.f ? acc.y : 0.01f * acc.y;
        acc.z = acc.z > 0.f ? acc.z : 0.01f * acc.z;
        acc.w = acc.w > 0.f ? acc.w : 0.01f * acc.w;
    }
    uint32_t h0, l0, h1, l1;
    split2(acc.x, acc.y, h0, l0);
    split2(acc.z, acc.w, h1, l1);
    outHi[(size_t)node * W4 + t] = make_uint2(h0, h1);
    outLo[(size_t)node * W4 + t] = make_uint2(l0, l1);
}

// scalar fp32-out SpMM for final layer (W=32)
__global__ void spmm_kernel32(const float* __restrict__ in, float* __restrict__ out,
                              const float* __restrict__ bias, int act) {
    int node = blockIdx.x;
    int tid = threadIdx.x;
    int s = g_rowptr[node], e = g_rowptr[node + 1];
    float acc = 0.f;
    int p = s;
    for (; p + 1 < e; p += 2) {
        int c0 = g_col[p], c1 = g_col[p + 1];
        float w0 = g_wgt[p], w1 = g_wgt[p + 1];
        acc += w0 * in[(size_t)c0 * 32 + tid] + w1 * in[(size_t)c1 * 32 + tid];
    }
    if (p < e) acc += g_wgt[p] * in[(size_t)g_col[p] * 32 + tid];
    float v = acc;
    if (bias) v += bias[tid];
    if (act == 1) v = fmaxf(v, 0.f);
    else if (act == 2) v = (v > 0.f) ? v : 0.01f * v;
    out[(size_t)node * 32 + tid] = v;
}

// ---------------- fused weight transpose + split ------------------------------
struct TParams { const float* W[9]; };
__global__ void transpose_all_kernel(TParams tp, float* wt9) {
    int l = blockIdx.z;
    int K = d_widths[l], N = d_widths[l + 1];
    int k0 = blockIdx.x * 32, n0 = blockIdx.y * 32;
    if (k0 >= K || n0 >= N) return;
    const float* W = tp.W[l];
    float* Wt = wt9 + (size_t)l * WMAX * WMAX;
    __shared__ float t[32][33];
    int x = threadIdx.x, y = threadIdx.y;
    for (int i = y; i < 32; i += 8) {
        int k = k0 + i, nn = n0 + x;
        t[i][x] = (k < K && nn < N) ? W[(size_t)k * N + nn] : 0.f;
    }
    __syncthreads();
    for (int i = y; i < 32; i += 8) {
        int nn = n0 + i, k = k0 + x;
        if (nn < N && k < K) Wt[(size_t)nn * K + k] = t[x][i];
    }
}
__global__ void split_w_kernel(const float* __restrict__ wt9,
                               uint32_t* __restrict__ whi, uint32_t* __restrict__ wlo,
                               int total_words) {
    int i = blockIdx.x * blockDim.x + threadIdx.x;
    if (i < total_words) {
        float x0 = wt9[2 * i], x1 = wt9[2 * i + 1];
        uint32_t h, l;
        split2(x0, x1, h, l);
        whi[i] = h;
        wlo[i] = l;
    }
}

// ---------------- 3xBF16 mma.sync GEMM (m16n8k16), cp.async pipelined ---------
// C[M,N] = A[M,K]*W^T with A,B given as pre-split bf16 hi/lo planes.
// BM=128, BN=128, BK=32, 256 thr, 8 warps (2x4). Smem plane stride 20 words.
#define S4 20
#define PLANE_WORDS (128 * S4)            // 2560 words per plane tile
#define STAGE_WORDS (4 * PLANE_WORDS)     // Ahi,Alo,Bhi,Blo
#define GEMM_SMEM_BYTES (2 * STAGE_WORDS * 4)   // 81920 B double buffered

__device__ __forceinline__ void mma16(float* d, const uint32_t* a, const uint32_t* b) {
    asm volatile(
        "mma.sync.aligned.m16n8k16.row.col.f32.bf16.bf16.f32 "
        "{%0,%1,%2,%3}, {%4,%5,%6,%7}, {%8,%9}, {%0,%1,%2,%3};"
        : "+f"(d[0]), "+f"(d[1]), "+f"(d[2]), "+f"(d[3])
        : "r"(a[0]), "r"(a[1]), "r"(a[2]), "r"(a[3]), "r"(b[0]), "r"(b[1]));
}
__device__ __forceinline__ void cp_async16(uint32_t dst, const void* src, int sz) {
    asm volatile("cp.async.ca.shared.global [%0], [%1], 16, %2;"
                 :: "r"(dst), "l"(src), "r"(sz) : "memory");
}

__global__ __launch_bounds__(256) void gemm_bf16x3_kernel(
    const uint32_t* __restrict__ Ahi, const uint32_t* __restrict__ Alo,
    const uint32_t* __restrict__ Bhi, const uint32_t* __restrict__ Blo,
    const float* __restrict__ bias, float* __restrict__ C,
    uint32_t* __restrict__ Ohi, uint32_t* __restrict__ Olo,
    int M, int K, int Nfull, int act, int outSplit)
{
    extern __shared__ uint32_t smw[];
    uint32_t sb = smem_u32(smw);
    int tid = threadIdx.x;
    int wid = tid >> 5, lid = tid & 31;
    int wm = wid >> 2;
    int wn = wid & 3;
    int g  = lid >> 2;
    int tg = lid & 3;
    int m0 = blockIdx.y * 128;
    int n0 = blockIdx.x * 128;
    int Kw = K >> 1;                 // plane row length in words

    float acc[4][4][4];
#pragma unroll
    for (int mi = 0; mi < 4; mi++)
#pragma unroll
        for (int ni = 0; ni < 4; ni++)
#pragma unroll
            for (int q = 0; q < 4; q++) acc[mi][ni][q] = 0.f;

    int KT = K >> 5;

    auto load_tile = [&](int kt, int b) {
        int kw = kt << 4;            // 16 words per chunk
        uint32_t base = sb + (uint32_t)(b * STAGE_WORDS) * 4u;
#pragma unroll
        for (int q = 0; q < 2; q++) {
            int i = tid + q * 256;
            int r = i >> 2, c = i & 3;
            uint32_t doff = (uint32_t)(r * S4 + c * 4) * 4u;
            bool okA = (m0 + r) < M;
            size_t sA = (size_t)(m0 + r) * Kw + kw + c * 4;
            cp_async16(base + doff, Ahi + sA, okA ? 16 : 0);
            cp_async16(base + PLANE_WORDS * 4u + doff, Alo + sA, okA ? 16 : 0);
            bool okB = (n0 + r) < Nfull;
            size_t sB = (size_t)(n0 + r) * Kw + kw + c * 4;
            cp_async16(base + 2u * PLANE_WORDS * 4u + doff, Bhi + sB, okB ? 16 : 0);
            cp_async16(base + 3u * PLANE_WORDS * 4u + doff, Blo + sB, okB ? 16 : 0);
        }
    };

    load_tile(0, 0);
    asm volatile("cp.async.commit_group;" ::: "memory");
    if (KT > 1) load_tile(1, 1);
    asm volatile("cp.async.commit_group;" ::: "memory");

    for (int kt = 0; kt < KT; kt++) {
        asm volatile("cp.async.wait_group 1;" ::: "memory");
        __syncthreads();
        const uint32_t* AH = smw + (kt & 1) * STAGE_WORDS;
        const uint32_t* AL = AH + PLANE_WORDS;
        const uint32_t* BH = AL + PLANE_WORDS;
        const uint32_t* BL = BH + PLANE_WORDS;

#pragma unroll
        for (int kk = 0; kk < 2; kk++) {
            int kb = kk * 8;
            uint32_t ah[4][4], al[4][4], bh[4][2], bl[4][2];
#pragma unroll
            for (int mi = 0; mi < 4; mi++) {
                int rb = wm * 64 + mi * 16;
                int o0 = (rb + g) * S4 + kb + tg;
                int o1 = (rb + g + 8) * S4 + kb + tg;
                ah[mi][0] = AH[o0]; ah[mi][1] = AH[o1];
                ah[mi][2] = AH[o0 + 4]; ah[mi][3] = AH[o1 + 4];
                al[mi][0] = AL[o0]; al[mi][1] = AL[o1];
                al[mi][2] = AL[o0 + 4]; al[mi][3] = AL[o1 + 4];
            }
#pragma unroll
            for (int ni = 0; ni < 4; ni++) {
                int nb = wn * 32 + ni * 8;
                int o = (nb + g) * S4 + kb + tg;
                bh[ni][0] = BH[o]; bh[ni][1] = BH[o + 4];
                bl[ni][0] = BL[o]; bl[ni][1] = BL[o + 4];
            }
#pragma unroll
            for (int mi = 0; mi < 4; mi++)
#pragma unroll
                for (int ni = 0; ni < 4; ni++) {
                    mma16(acc[mi][ni], ah[mi], bh[ni]);
                    mma16(acc[mi][ni], ah[mi], bl[ni]);
                    mma16(acc[mi][ni], al[mi], bh[ni]);
                }
        }
        __syncthreads();
        if (kt + 2 < KT) load_tile(kt + 2, kt & 1);
        asm volatile("cp.async.commit_group;" ::: "memory");
    }

    // epilogue: bias + activation; fp32 store or split-bf16 plane store
#pragma unroll
    for (int mi = 0; mi < 4; mi++) {
        int row0 = m0 + wm * 64 + mi * 16 + g;
        int row1 = row0 + 8;
#pragma unroll
        for (int ni = 0; ni < 4; ni++) {
            int col = n0 + wn * 32 + ni * 8 + 2 * tg;
            if (col >= Nfull) continue;
            float bx = 0.f, by = 0.f;
            if (bias) { bx = bias[col]; by = bias[col + 1]; }
#pragma unroll
            for (int h = 0; h < 2; h++) {
                int row = h ? row1 : row0;
                if (row >= M) continue;
                float vx = acc[mi][ni][h * 2 + 0] + bx;
                float vy = acc[mi][ni][h * 2 + 1] + by;
                if (act == 1) { vx = fmaxf(vx, 0.f); vy = fmaxf(vy, 0.f); }
                else if (act == 2) {
                    vx = vx > 0.f ? vx : 0.01f * vx;
                    vy = vy > 0.f ? vy : 0.01f * vy;
                }
                if (outSplit) {
                    uint32_t hw, lw;
                    split2(vx, vy, hw, lw);
                    size_t widx = (size_t)row * (Nfull >> 1) + (col >> 1);
                    Ohi[widx] = hw;
                    Olo[widx] = lw;
                } else {
                    *(float2*)(C + (size_t)row * Nfull + col) = make_float2(vx, vy);
                }
            }
        }
    }
}

// ---------------- mean pool ---------------------------------------------------
__global__ void zero_pool_kernel() {
    int i = blockIdx.x * blockDim.x + threadIdx.x;
    if (i < N_GRAPHS * 32) g_pool[i] = 0.f;
    if (i < N_GRAPHS) g_pcnt[i] = 0;
}
__global__ void pool_cnt_kernel(const void* batch, int n) {
    int i = blockIdx.x * blockDim.x + threadIdx.x;
    if (i < n) atomicAdd(&g_pcnt[ld_idx(batch, i)], 1);
}
__global__ void pool_sum_kernel(const float* __restrict__ h, const void* batch, int n) {
    int idx = blockIdx.x * blockDim.x + threadIdx.x;
    if (idx < n * 32) {
        int node = idx >> 5;
        int c = idx & 31;
        int b = ld_idx(batch, node);
        atomicAdd(&g_pool[b * 32 + c], h[(size_t)node * 32 + c]);
    }
}
__global__ void pool_fin_kernel(float* out) {
    int i = blockIdx.x * blockDim.x + threadIdx.x;
    if (i < N_GRAPHS * 32) {
        int b = i >> 5;
        out[i] = g_pool[i] / fmaxf((float)g_pcnt[b], 1.0f);
    }
}

// ---------------- host driver --------------------------------------------------
static inline int cdiv(int a, int b) { return (a + b - 1) / b; }

extern "C" void kernel_launch(void* const* d_in, const int* in_sizes, int n_in,
                              void* d_out, int out_size) {
    const float* x     = (const float*)d_in[0];
    const void*  edge  = d_in[1];
    const void*  batch = d_in[2];
    TParams tp;
    const float* bl[9];
    for (int i = 0; i < 9; i++) {
        tp.W[i] = (const float*)d_in[3 + 2 * i];
        bl[i]   = (const float*)d_in[4 + 2 * i];
    }
    int n = in_sizes[2];
    int E = in_sizes[1] / 2;

    float *F, *out32, *wt9;
    uint32_t *hi1, *lo1, *hi2, *lo2, *whi, *wlo;
    cudaGetSymbolAddress((void**)&F,    g_F);
    cudaGetSymbolAddress((void**)&out32, g_out32);
    cudaGetSymbolAddress((void**)&wt9,  g_wt9);
    cudaGetSymbolAddress((void**)&hi1,  g_hi1);
    cudaGetSymbolAddress((void**)&lo1,  g_lo1);
    cudaGetSymbolAddress((void**)&hi2,  g_hi2);
    cudaGetSymbolAddress((void**)&lo2,  g_lo2);
    cudaGetSymbolAddress((void**)&whi,  g_whi);
    cudaGetSymbolAddress((void**)&wlo,  g_wlo);

    cudaFuncSetAttribute(gemm_bf16x3_kernel, cudaFuncAttributeMaxDynamicSharedMemorySize,
                         GEMM_SMEM_BYTES);

    // --- CSR build + weight transpose/split ---
    detect_kernel<<<1, 1>>>(edge);
    transpose_all_kernel<<<dim3(16, 16, 9), dim3(32, 8)>>>(tp, wt9);
    split_w_kernel<<<cdiv(9 * WMAX * WMAX / 2, 256), 256>>>(wt9, whi, wlo, 9 * WMAX * WMAX / 2);
    init_cnt_kernel<<<cdiv(n, 256), 256>>>(n);
    count_kernel<<<cdiv(E, 256), 256>>>(edge, E);
    dinv_kernel<<<cdiv(n, 256), 256>>>(n);
    scan_kernel<<<1, 1024>>>(n);
    fill_edges_kernel<<<cdiv(E, 256), 256>>>(edge, E);
    fill_loops_kernel<<<cdiv(n, 256), 256>>>(n);

    // --- layers ---
    static const int widths[10]  = {128, 128, 256, 384, 512, 512, 384, 256, 128, 32};
    static const int acts[9]     = {1, 1, 2, 1, 2, 2, 1, 1, 0};
    static const int aggfirst[9] = {1, 1, 1, 1, 1, 0, 0, 0, 0};

    const float* fin = x;   // fp32 input for the next spmm
    for (int l = 0; l < 9; l++) {
        int K = widths[l], N = widths[l + 1];
        const uint32_t* wh = whi + (size_t)l * WMAX * WMAX / 2;
        const uint32_t* wl_ = wlo + (size_t)l * WMAX * WMAX / 2;
        dim3 grid(cdiv(N, 128), cdiv(n, 128));
        if (aggfirst[l]) {
            // spmm (fp32 in -> split planes), then gemm (planes -> fp32 F, or planes2 for l==4)
            spmm4_split_kernel<<<n, K / 4>>>((const float4*)fin, (uint2*)hi1, (uint2*)lo1,
                                             nullptr, 0);
            int osplit = (l == 4) ? 1 : 0;
            gemm_bf16x3_kernel<<<grid, 256, GEMM_SMEM_BYTES>>>(
                hi1, lo1, wh, wl_, bl[l], F, hi2, lo2, n, K, N, acts[l], osplit);
            fin = F;
        } else if (l < 8) {
            // gemm (planes -> fp32 F), then spmm (F -> split planes, bias+act)
            const uint32_t* ih = (l == 5) ? hi2 : hi1;
            const uint32_t* il = (l == 5) ? lo2 : lo1;
            gemm_bf16x3_kernel<<<grid, 256, GEMM_SMEM_BYTES>>>(
                ih, il, wh, wl_, nullptr, F, nullptr, nullptr, n, K, N, 0, 0);
            spmm4_split_kernel<<<n, N / 4>>>((const float4*)F, (uint2*)hi1, (uint2*)lo1,
                                             (const float4*)bl[l], acts[l]);
        } else {
            // final layer: gemm (planes -> fp32 F at W=32), spmm32 (F -> out32 fp32)
            gemm_bf16x3_kernel<<<grid, 256, GEMM_SMEM_BYTES>>>(
                hi1, lo1, wh, wl_, nullptr, F, nullptr, nullptr, n, K, N, 0, 0);
            spmm_kernel32<<<n, 32>>>(F, out32, bl[l], 0);
        }
    }

    // --- pool ---
    zero_pool_kernel<<<cdiv(N_GRAPHS * 32, 256), 256>>>();
    pool_cnt_kernel<<<cdiv(n, 256), 256>>>(batch, n);
    pool_sum_kernel<<<cdiv(n * 32, 256), 256>>>(out32, batch, n);
    pool_fin_kernel<<<cdiv(N_GRAPHS * 32, 256), 256>>>((float*)d_out);
}

// round 6
// speedup vs baseline: 2.5308x; 1.1975x over previous
#include <cuda_runtime.h>
#include <cuda_fp16.h>
#include <cstdint>

#define N_MAX   50000
#define E_MAX   1700000
#define WMAX    512
#define N_GRAPHS 64

// ---------------- scratch (device globals) ----------------------------------
__device__ float    g_F[(size_t)N_MAX * 32];                   // fp32 (final gemm out)
__device__ float    g_out32[(size_t)N_MAX * 32];               // final layer fp32
__device__ uint4    g_H[(size_t)N_MAX * WMAX / 8];             // fp16 feature buffer
__device__ uint32_t g_hi1[(size_t)N_MAX * WMAX / 2];           // bf16 hi plane (pair 1)
__device__ uint32_t g_lo1[(size_t)N_MAX * WMAX / 2];
__device__ uint32_t g_hi2[(size_t)N_MAX * WMAX / 2];           // pair 2 (layer-4 handoff)
__device__ uint32_t g_lo2[(size_t)N_MAX * WMAX / 2];
__device__ float    g_wt9[(size_t)9 * WMAX * WMAX];            // fp32 transposed weights
__device__ uint32_t g_whi[(size_t)9 * WMAX * WMAX / 2];        // weight bf16 planes
__device__ uint32_t g_wlo[(size_t)9 * WMAX * WMAX / 2];
__device__ float    g_dinv[N_MAX];
__device__ int      g_cnt[N_MAX];
__device__ int      g_rowptr[N_MAX + 1];
__device__ int      g_cur[N_MAX];
__device__ int      g_col[E_MAX];
__device__ float    g_wgt[E_MAX];
__device__ float    g_pool[N_GRAPHS * 32];
__device__ int      g_pcnt[N_GRAPHS];
__device__ int      g_is64;

__device__ const int d_widths[10] = {128, 128, 256, 384, 512, 512, 384, 256, 128, 32};

// ---------------- helpers -----------------------------------------------------
__device__ __forceinline__ uint32_t smem_u32(const void* p) {
    uint32_t a;
    asm("{ .reg .u64 t; cvta.to.shared.u64 t, %1; cvt.u32.u64 %0, t; }" : "=r"(a) : "l"(p));
    return a;
}
__device__ __forceinline__ int ld_idx(const void* p, long i) {
    if (g_is64) return (int)((const long long*)p)[i];
    return ((const int*)p)[i];
}
// split two consecutive floats into packed bf16x2 hi/lo words (low 16 = first elem)
__device__ __forceinline__ void split2(float x0, float x1, uint32_t& hi, uint32_t& lo) {
    uint32_t h;
    asm("cvt.rn.bf16x2.f32 %0, %1, %2;" : "=r"(h) : "f"(x1), "f"(x0));
    float h0 = __uint_as_float(h << 16);
    float h1 = __uint_as_float(h & 0xFFFF0000u);
    float r0 = x0 - h0, r1 = x1 - h1;
    asm("cvt.rn.bf16x2.f32 %0, %1, %2;" : "=r"(lo) : "f"(r1), "f"(r0));
    hi = h;
}
__global__ void detect_kernel(const void* edge) {
    const int* p = (const int*)edge;
    bool is64 = true;
    for (int i = 0; i < 8; i++)
        if (p[2 * i + 1] != 0) is64 = false;
    g_is64 = is64 ? 1 : 0;
}

// ---------------- CSR build ---------------------------------------------------
__global__ void init_cnt_kernel(int n) {
    int i = blockIdx.x * blockDim.x + threadIdx.x;
    if (i < n) g_cnt[i] = 1;
}
__global__ void count_kernel(const void* edge, int E) {
    int e = blockIdx.x * blockDim.x + threadIdx.x;
    if (e < E) atomicAdd(&g_cnt[ld_idx(edge, (long)E + e)], 1);
}
__global__ void dinv_kernel(int n) {
    int i = blockIdx.x * blockDim.x + threadIdx.x;
    if (i < n) g_dinv[i] = rsqrtf((float)g_cnt[i]);
}
__global__ void scan_kernel(int n) {
    __shared__ int sh[1024];
    __shared__ int carry_s;
    int tid = threadIdx.x;
    if (tid == 0) carry_s = 0;
    __syncthreads();
    for (int base = 0; base < n; base += 1024) {
        int i = base + tid;
        int v = (i < n) ? g_cnt[i] : 0;
        sh[tid] = v;
        __syncthreads();
        for (int off = 1; off < 1024; off <<= 1) {
            int t = (tid >= off) ? sh[tid - off] : 0;
            __syncthreads();
            sh[tid] += t;
            __syncthreads();
        }
        int carry = carry_s;
        if (i < n) {
            int excl = carry + sh[tid] - v;
            g_rowptr[i] = excl;
            g_cur[i] = excl;
        }
        __syncthreads();
        if (tid == 1023) carry_s = carry + sh[1023];
        __syncthreads();
    }
    if (tid == 0) g_rowptr[n] = carry_s;
}
__global__ void fill_edges_kernel(const void* edge, int E) {
    int e = blockIdx.x * blockDim.x + threadIdx.x;
    if (e < E) {
        int src = ld_idx(edge, e);
        int dst = ld_idx(edge, (long)E + e);
        int pos = atomicAdd(&g_cur[dst], 1);
        g_col[pos] = src;
        g_wgt[pos] = g_dinv[src] * g_dinv[dst];
    }
}
__global__ void fill_loops_kernel(int n) {
    int i = blockIdx.x * blockDim.x + threadIdx.x;
    if (i < n) {
        int pos = atomicAdd(&g_cur[i], 1);
        g_col[pos] = i;
        g_wgt[pos] = g_dinv[i] * g_dinv[i];
    }
}

// ---------------- SpMM (fp16 gather, fp32 accumulate, split-bf16 out) ---------
__device__ __forceinline__ void acc8(float* acc, const uint4& v, float w) {
    float2 f0 = __half22float2(*(const half2*)&v.x);
    float2 f1 = __half22float2(*(const half2*)&v.y);
    float2 f2 = __half22float2(*(const half2*)&v.z);
    float2 f3 = __half22float2(*(const half2*)&v.w);
    acc[0] += w * f0.x; acc[1] += w * f0.y;
    acc[2] += w * f1.x; acc[3] += w * f1.y;
    acc[4] += w * f2.x; acc[5] += w * f2.y;
    acc[6] += w * f3.x; acc[7] += w * f3.y;
}

__global__ void spmm_h_kernel(const uint4* __restrict__ in,
                              uint4* __restrict__ outHi, uint4* __restrict__ outLo,
                              const float* __restrict__ bias, int act, int W8, int n) {
    int node = blockIdx.x * blockDim.y + threadIdx.y;
    if (node >= n) return;
    int t = threadIdx.x;                 // 0..W8-1, covers cols 8t..8t+7
    int s = g_rowptr[node], e = g_rowptr[node + 1];
    float acc[8];
#pragma unroll
    for (int j = 0; j < 8; j++) acc[j] = 0.f;
    int p = s;
    for (; p + 3 < e; p += 4) {
        int c0 = g_col[p], c1 = g_col[p + 1], c2 = g_col[p + 2], c3 = g_col[p + 3];
        float w0 = g_wgt[p], w1 = g_wgt[p + 1], w2 = g_wgt[p + 2], w3 = g_wgt[p + 3];
        uint4 v0 = in[(size_t)c0 * W8 + t];
        uint4 v1 = in[(size_t)c1 * W8 + t];
        uint4 v2 = in[(size_t)c2 * W8 + t];
        uint4 v3 = in[(size_t)c3 * W8 + t];
        acc8(acc, v0, w0); acc8(acc, v1, w1);
        acc8(acc, v2, w2); acc8(acc, v3, w3);
    }
    for (; p < e; p++) {
        uint4 v0 = in[(size_t)g_col[p] * W8 + t];
        acc8(acc, v0, g_wgt[p]);
    }
    if (bias) {
#pragma unroll
        for (int j = 0; j < 8; j++) acc[j] += bias[8 * t + j];
    }
    if (act == 1) {
#pragma unroll
        for (int j = 0; j < 8; j++) acc[j] = fmaxf(acc[j], 0.f);
    } else if (act == 2) {
#pragma unroll
        for (int j = 0; j < 8; j++) acc[j] = acc[j] > 0.f ? acc[j] : 0.01f * acc[j];
    }
    uint4 hw, lw;
    split2(acc[0], acc[1], hw.x, lw.x);
    split2(acc[2], acc[3], hw.y, lw.y);
    split2(acc[4], acc[5], hw.z, lw.z);
    split2(acc[6], acc[7], hw.w, lw.w);
    outHi[(size_t)node * W8 + t] = hw;
    outLo[(size_t)node * W8 + t] = lw;
}

// fp32 scalar SpMM for final layer (W=32)
__global__ void spmm_kernel32(const float* __restrict__ in, float* __restrict__ out,
                              const float* __restrict__ bias, int act) {
    int node = blockIdx.x;
    int tid = threadIdx.x;
    int s = g_rowptr[node], e = g_rowptr[node + 1];
    float acc = 0.f;
    int p = s;
    for (; p + 1 < e; p += 2) {
        int c0 = g_col[p], c1 = g_col[p + 1];
        float w0 = g_wgt[p], w1 = g_wgt[p + 1];
        acc += w0 * in[(size_t)c0 * 32 + tid] + w1 * in[(size_t)c1 * 32 + tid];
    }
    if (p < e) acc += g_wgt[p] * in[(size_t)g_col[p] * 32 + tid];
    float v = acc;
    if (bias) v += bias[tid];
    if (act == 1) v = fmaxf(v, 0.f);
    else if (act == 2) v = (v > 0.f) ? v : 0.01f * v;
    out[(size_t)node * 32 + tid] = v;
}

// ---------------- x -> fp16 convert -------------------------------------------
__global__ void f2h_kernel(const float2* __restrict__ in, uint32_t* __restrict__ out,
                           long total2) {
    long i = (long)blockIdx.x * blockDim.x + threadIdx.x;
    if (i < total2) {
        float2 v = in[i];
        half2 h = __float22half2_rn(v);
        out[i] = *(uint32_t*)&h;
    }
}

// ---------------- fused weight transpose + split ------------------------------
struct TParams { const float* W[9]; };
__global__ void transpose_all_kernel(TParams tp, float* wt9) {
    int l = blockIdx.z;
    int K = d_widths[l], N = d_widths[l + 1];
    int k0 = blockIdx.x * 32, n0 = blockIdx.y * 32;
    if (k0 >= K || n0 >= N) return;
    const float* W = tp.W[l];
    float* Wt = wt9 + (size_t)l * WMAX * WMAX;
    __shared__ float t[32][33];
    int x = threadIdx.x, y = threadIdx.y;
    for (int i = y; i < 32; i += 8) {
        int k = k0 + i, nn = n0 + x;
        t[i][x] = (k < K && nn < N) ? W[(size_t)k * N + nn] : 0.f;
    }
    __syncthreads();
    for (int i = y; i < 32; i += 8) {
        int nn = n0 + i, k = k0 + x;
        if (nn < N && k < K) Wt[(size_t)nn * K + k] = t[x][i];
    }
}
__global__ void split_w_kernel(const float* __restrict__ wt9,
                               uint32_t* __restrict__ whi, uint32_t* __restrict__ wlo,
                               int total_words) {
    int i = blockIdx.x * blockDim.x + threadIdx.x;
    if (i < total_words) {
        float x0 = wt9[2 * i], x1 = wt9[2 * i + 1];
        uint32_t h, l;
        split2(x0, x1, h, l);
        whi[i] = h;
        wlo[i] = l;
    }
}

// ---------------- 3xBF16 mma.sync GEMM (m16n8k16), cp.async pipelined ---------
#define S4 20
#define PLANE_WORDS (128 * S4)
#define STAGE_WORDS (4 * PLANE_WORDS)
#define GEMM_SMEM_BYTES (2 * STAGE_WORDS * 4)

__device__ __forceinline__ void mma16(float* d, const uint32_t* a, const uint32_t* b) {
    asm volatile(
        "mma.sync.aligned.m16n8k16.row.col.f32.bf16.bf16.f32 "
        "{%0,%1,%2,%3}, {%4,%5,%6,%7}, {%8,%9}, {%0,%1,%2,%3};"
        : "+f"(d[0]), "+f"(d[1]), "+f"(d[2]), "+f"(d[3])
        : "r"(a[0]), "r"(a[1]), "r"(a[2]), "r"(a[3]), "r"(b[0]), "r"(b[1]));
}
__device__ __forceinline__ void cp_async16(uint32_t dst, const void* src, int sz) {
    asm volatile("cp.async.ca.shared.global [%0], [%1], 16, %2;"
                 :: "r"(dst), "l"(src), "r"(sz) : "memory");
}

// mode: 0 = fp32 out (C), 1 = split bf16 planes (Ohi/Olo), 2 = fp16 out (Oh)
__global__ __launch_bounds__(256) void gemm_bf16x3_kernel(
    const uint32_t* __restrict__ Ahi, const uint32_t* __restrict__ Alo,
    const uint32_t* __restrict__ Bhi, const uint32_t* __restrict__ Blo,
    const float* __restrict__ bias, float* __restrict__ C,
    uint32_t* __restrict__ Ohi, uint32_t* __restrict__ Olo,
    uint32_t* __restrict__ Oh,
    int M, int K, int Nfull, int act, int mode)
{
    extern __shared__ uint32_t smw[];
    uint32_t sb = smem_u32(smw);
    int tid = threadIdx.x;
    int wid = tid >> 5, lid = tid & 31;
    int wm = wid >> 2;
    int wn = wid & 3;
    int g  = lid >> 2;
    int tg = lid & 3;
    int m0 = blockIdx.y * 128;
    int n0 = blockIdx.x * 128;
    int Kw = K >> 1;

    float acc[4][4][4];
#pragma unroll
    for (int mi = 0; mi < 4; mi++)
#pragma unroll
        for (int ni = 0; ni < 4; ni++)
#pragma unroll
            for (int q = 0; q < 4; q++) acc[mi][ni][q] = 0.f;

    int KT = K >> 5;

    auto load_tile = [&](int kt, int b) {
        int kw = kt << 4;
        uint32_t base = sb + (uint32_t)(b * STAGE_WORDS) * 4u;
#pragma unroll
        for (int q = 0; q < 2; q++) {
            int i = tid + q * 256;
            int r = i >> 2, c = i & 3;
            uint32_t doff = (uint32_t)(r * S4 + c * 4) * 4u;
            bool okA = (m0 + r) < M;
            size_t sA = (size_t)(m0 + r) * Kw + kw + c * 4;
            cp_async16(base + doff, Ahi + sA, okA ? 16 : 0);
            cp_async16(base + PLANE_WORDS * 4u + doff, Alo + sA, okA ? 16 : 0);
            bool okB = (n0 + r) < Nfull;
            size_t sB = (size_t)(n0 + r) * Kw + kw + c * 4;
            cp_async16(base + 2u * PLANE_WORDS * 4u + doff, Bhi + sB, okB ? 16 : 0);
            cp_async16(base + 3u * PLANE_WORDS * 4u + doff, Blo + sB, okB ? 16 : 0);
        }
    };

    load_tile(0, 0);
    asm volatile("cp.async.commit_group;" ::: "memory");
    if (KT > 1) load_tile(1, 1);
    asm volatile("cp.async.commit_group;" ::: "memory");

    for (int kt = 0; kt < KT; kt++) {
        asm volatile("cp.async.wait_group 1;" ::: "memory");
        __syncthreads();
        const uint32_t* AH = smw + (kt & 1) * STAGE_WORDS;
        const uint32_t* AL = AH + PLANE_WORDS;
        const uint32_t* BH = AL + PLANE_WORDS;
        const uint32_t* BL = BH + PLANE_WORDS;

#pragma unroll
        for (int kk = 0; kk < 2; kk++) {
            int kb = kk * 8;
            uint32_t ah[4][4], al[4][4], bh[4][2], bl[4][2];
#pragma unroll
            for (int mi = 0; mi < 4; mi++) {
                int rb = wm * 64 + mi * 16;
                int o0 = (rb + g) * S4 + kb + tg;
                int o1 = (rb + g + 8) * S4 + kb + tg;
                ah[mi][0] = AH[o0]; ah[mi][1] = AH[o1];
                ah[mi][2] = AH[o0 + 4]; ah[mi][3] = AH[o1 + 4];
                al[mi][0] = AL[o0]; al[mi][1] = AL[o1];
                al[mi][2] = AL[o0 + 4]; al[mi][3] = AL[o1 + 4];
            }
#pragma unroll
            for (int ni = 0; ni < 4; ni++) {
                int nb = wn * 32 + ni * 8;
                int o = (nb + g) * S4 + kb + tg;
                bh[ni][0] = BH[o]; bh[ni][1] = BH[o + 4];
                bl[ni][0] = BL[o]; bl[ni][1] = BL[o + 4];
            }
#pragma unroll
            for (int mi = 0; mi < 4; mi++)
#pragma unroll
                for (int ni = 0; ni < 4; ni++) {
                    mma16(acc[mi][ni], ah[mi], bh[ni]);
                    mma16(acc[mi][ni], ah[mi], bl[ni]);
                    mma16(acc[mi][ni], al[mi], bh[ni]);
                }
        }
        __syncthreads();
        if (kt + 2 < KT) load_tile(kt + 2, kt & 1);
        asm volatile("cp.async.commit_group;" ::: "memory");
    }

    // epilogue
#pragma unroll
    for (int mi = 0; mi < 4; mi++) {
        int row0 = m0 + wm * 64 + mi * 16 + g;
        int row1 = row0 + 8;
#pragma unroll
        for (int ni = 0; ni < 4; ni++) {
            int col = n0 + wn * 32 + ni * 8 + 2 * tg;
            if (col >= Nfull) continue;
            float bx = 0.f, by = 0.f;
            if (bias) { bx = bias[col]; by = bias[col + 1]; }
#pragma unroll
            for (int h = 0; h < 2; h++) {
                int row = h ? row1 : row0;
                if (row >= M) continue;
                float vx = acc[mi][ni][h * 2 + 0] + bx;
                float vy = acc[mi][ni][h * 2 + 1] + by;
                if (act == 1) { vx = fmaxf(vx, 0.f); vy = fmaxf(vy, 0.f); }
                else if (act == 2) {
                    vx = vx > 0.f ? vx : 0.01f * vx;
                    vy = vy > 0.f ? vy : 0.01f * vy;
                }
                if (mode == 1) {
                    uint32_t hw, lw;
                    split2(vx, vy, hw, lw);
                    size_t widx = (size_t)row * (Nfull >> 1) + (col >> 1);
                    Ohi[widx] = hw;
                    Olo[widx] = lw;
                } else if (mode == 2) {
                    half2 hv = __float22half2_rn(make_float2(vx, vy));
                    Oh[(size_t)row * (Nfull >> 1) + (col >> 1)] = *(uint32_t*)&hv;
                } else {
                    *(float2*)(C + (size_t)row * Nfull + col) = make_float2(vx, vy);
                }
            }
        }
    }
}

// ---------------- mean pool ---------------------------------------------------
__global__ void zero_pool_kernel() {
    int i = blockIdx.x * blockDim.x + threadIdx.x;
    if (i < N_GRAPHS * 32) g_pool[i] = 0.f;
    if (i < N_GRAPHS) g_pcnt[i] = 0;
}
__global__ void pool_cnt_kernel(const void* batch, int n) {
    int i = blockIdx.x * blockDim.x + threadIdx.x;
    if (i < n) atomicAdd(&g_pcnt[ld_idx(batch, i)], 1);
}
__global__ void pool_sum_kernel(const float* __restrict__ h, const void* batch, int n) {
    int idx = blockIdx.x * blockDim.x + threadIdx.x;
    if (idx < n * 32) {
        int node = idx >> 5;
        int c = idx & 31;
        int b = ld_idx(batch, node);
        atomicAdd(&g_pool[b * 32 + c], h[(size_t)node * 32 + c]);
    }
}
__global__ void pool_fin_kernel(float* out) {
    int i = blockIdx.x * blockDim.x + threadIdx.x;
    if (i < N_GRAPHS * 32) {
        int b = i >> 5;
        out[i] = g_pool[i] / fmaxf((float)g_pcnt[b], 1.0f);
    }
}

// ---------------- host driver --------------------------------------------------
static inline int cdiv(int a, int b) { return (a + b - 1) / b; }

static void spmm_h_launch(const uint4* in, uint4* oh, uint4* ol,
                          const float* bias, int act, int W, int n) {
    int W8 = W / 8;
    int ypb = 128 / W8; if (ypb < 1) ypb = 1;
    dim3 blk(W8, ypb);
    spmm_h_kernel<<<cdiv(n, ypb), blk>>>(in, oh, ol, bias, act, W8, n);
}

extern "C" void kernel_launch(void* const* d_in, const int* in_sizes, int n_in,
                              void* d_out, int out_size) {
    const float* x     = (const float*)d_in[0];
    const void*  edge  = d_in[1];
    const void*  batch = d_in[2];
    TParams tp;
    const float* bl[9];
    for (int i = 0; i < 9; i++) {
        tp.W[i] = (const float*)d_in[3 + 2 * i];
        bl[i]   = (const float*)d_in[4 + 2 * i];
    }
    int n = in_sizes[2];
    int E = in_sizes[1] / 2;

    float *F, *out32, *wt9;
    uint4 *H;
    uint32_t *hi1, *lo1, *hi2, *lo2, *whi, *wlo;
    cudaGetSymbolAddress((void**)&F,     g_F);
    cudaGetSymbolAddress((void**)&out32, g_out32);
    cudaGetSymbolAddress((void**)&H,     g_H);
    cudaGetSymbolAddress((void**)&wt9,   g_wt9);
    cudaGetSymbolAddress((void**)&hi1,   g_hi1);
    cudaGetSymbolAddress((void**)&lo1,   g_lo1);
    cudaGetSymbolAddress((void**)&hi2,   g_hi2);
    cudaGetSymbolAddress((void**)&lo2,   g_lo2);
    cudaGetSymbolAddress((void**)&whi,   g_whi);
    cudaGetSymbolAddress((void**)&wlo,   g_wlo);

    cudaFuncSetAttribute(gemm_bf16x3_kernel, cudaFuncAttributeMaxDynamicSharedMemorySize,
                         GEMM_SMEM_BYTES);

    // --- CSR build + weight transpose/split + x->fp16 ---
    detect_kernel<<<1, 1>>>(edge);
    transpose_all_kernel<<<dim3(16, 16, 9), dim3(32, 8)>>>(tp, wt9);
    split_w_kernel<<<cdiv(9 * WMAX * WMAX / 2, 256), 256>>>(wt9, whi, wlo, 9 * WMAX * WMAX / 2);
    f2h_kernel<<<cdiv(n * 64, 256), 256>>>((const float2*)x, (uint32_t*)H, (long)n * 64);
    init_cnt_kernel<<<cdiv(n, 256), 256>>>(n);
    count_kernel<<<cdiv(E, 256), 256>>>(edge, E);
    dinv_kernel<<<cdiv(n, 256), 256>>>(n);
    scan_kernel<<<1, 1024>>>(n);
    fill_edges_kernel<<<cdiv(E, 256), 256>>>(edge, E);
    fill_loops_kernel<<<cdiv(n, 256), 256>>>(n);

    // --- layers ---
    static const int widths[10]  = {128, 128, 256, 384, 512, 512, 384, 256, 128, 32};
    static const int acts[9]     = {1, 1, 2, 1, 2, 2, 1, 1, 0};
    static const int aggfirst[9] = {1, 1, 1, 1, 1, 0, 0, 0, 0};

    for (int l = 0; l < 9; l++) {
        int K = widths[l], N = widths[l + 1];
        const uint32_t* wh  = whi + (size_t)l * WMAX * WMAX / 2;
        const uint32_t* wl_ = wlo + (size_t)l * WMAX * WMAX / 2;
        dim3 grid(cdiv(N, 128), cdiv(n, 128));
        if (aggfirst[l]) {
            // spmm (fp16 H -> split planes), gemm (planes -> fp16 H | planes2 for l==4)
            spmm_h_launch(H, (uint4*)hi1, (uint4*)lo1, nullptr, 0, K, n);
            int mode = (l == 4) ? 1 : 2;
            gemm_bf16x3_kernel<<<grid, 256, GEMM_SMEM_BYTES>>>(
                hi1, lo1, wh, wl_, bl[l], nullptr, hi2, lo2, (uint32_t*)H,
                n, K, N, acts[l], mode);
        } else if (l < 8) {
            // gemm (planes -> fp16 H, no bias), spmm (H -> split planes, bias+act)
            const uint32_t* ih = (l == 5) ? hi2 : hi1;
            const uint32_t* il = (l == 5) ? lo2 : lo1;
            gemm_bf16x3_kernel<<<grid, 256, GEMM_SMEM_BYTES>>>(
                ih, il, wh, wl_, nullptr, nullptr, nullptr, nullptr, (uint32_t*)H,
                n, K, N, 0, 2);
            spmm_h_launch(H, (uint4*)hi1, (uint4*)lo1, bl[l], acts[l], N, n);
        } else {
            // final layer: gemm (planes -> fp32 F), spmm32 (F -> out32)
            gemm_bf16x3_kernel<<<grid, 256, GEMM_SMEM_BYTES>>>(
                hi1, lo1, wh, wl_, nullptr, F, nullptr, nullptr, nullptr,
                n, K, N, 0, 0);
            spmm_kernel32<<<n, 32>>>(F, out32, bl[l], 0);
        }
    }

    // --- pool ---
    zero_pool_kernel<<<cdiv(N_GRAPHS * 32, 256), 256>>>();
    pool_cnt_kernel<<<cdiv(n, 256), 256>>>(batch, n);
    pool_sum_kernel<<<cdiv(n * 32, 256), 256>>>(out32, batch, n);
    pool_fin_kernel<<<cdiv(N_GRAPHS * 32, 256), 256>>>((float*)d_out);
}

// round 7
// speedup vs baseline: 3.0826x; 1.2181x over previous
#include <cuda_runtime.h>
#include <cuda_fp16.h>
#include <cstdint>

#define N_MAX   50000
#define E_MAX   1700000
#define WMAX    512
#define N_GRAPHS 64

// ---------------- scratch (device globals) ----------------------------------
__device__ float    g_F[(size_t)N_MAX * 32];                   // final gemm out fp32
__device__ float    g_out32[(size_t)N_MAX * 32];               // final layer fp32
__device__ uint4    g_H0[(size_t)N_MAX * WMAX / 8];            // fp16 activations (ping)
__device__ uint4    g_H1[(size_t)N_MAX * WMAX / 8];            // fp16 activations (pong)
__device__ uint4    g_Ht[(size_t)N_MAX * WMAX / 8];            // fp16 temp (agg)
__device__ float    g_wt9[(size_t)9 * WMAX * WMAX];            // fp32 transposed weights
__device__ uint32_t g_whi[(size_t)9 * WMAX * WMAX / 2];        // weight fp16 hi plane
__device__ uint32_t g_wlo[(size_t)9 * WMAX * WMAX / 2];        // weight fp16 lo plane
__device__ float    g_dinv[N_MAX];
__device__ int      g_cnt[N_MAX];
__device__ int      g_rowptr[N_MAX + 1];
__device__ int      g_cur[N_MAX];
__device__ int      g_col[E_MAX];
__device__ float    g_wgt[E_MAX];
__device__ float    g_pool[N_GRAPHS * 32];
__device__ int      g_pcnt[N_GRAPHS];
__device__ int      g_is64;

__device__ const int d_widths[10] = {128, 128, 256, 384, 512, 512, 384, 256, 128, 32};

// ---------------- helpers -----------------------------------------------------
__device__ __forceinline__ uint32_t smem_u32(const void* p) {
    uint32_t a;
    asm("{ .reg .u64 t; cvta.to.shared.u64 t, %1; cvt.u32.u64 %0, t; }" : "=r"(a) : "l"(p));
    return a;
}
__device__ __forceinline__ int ld_idx(const void* p, long i) {
    if (g_is64) return (int)((const long long*)p)[i];
    return ((const int*)p)[i];
}
// split two floats into packed fp16x2 hi/lo words
__device__ __forceinline__ void split2h(float x0, float x1, uint32_t& hi, uint32_t& lo) {
    half2 h = __float22half2_rn(make_float2(x0, x1));
    float2 hf = __half22float2(h);
    half2 l = __float22half2_rn(make_float2(x0 - hf.x, x1 - hf.y));
    hi = *(uint32_t*)&h;
    lo = *(uint32_t*)&l;
}
__global__ void detect_kernel(const void* edge) {
    const int* p = (const int*)edge;
    bool is64 = true;
    for (int i = 0; i < 8; i++)
        if (p[2 * i + 1] != 0) is64 = false;
    g_is64 = is64 ? 1 : 0;
}

// ---------------- CSR build ---------------------------------------------------
__global__ void init_cnt_kernel(int n) {
    int i = blockIdx.x * blockDim.x + threadIdx.x;
    if (i < n) g_cnt[i] = 1;
}
__global__ void count_kernel(const void* edge, int E) {
    int e = blockIdx.x * blockDim.x + threadIdx.x;
    if (e < E) atomicAdd(&g_cnt[ld_idx(edge, (long)E + e)], 1);
}
__global__ void dinv_kernel(int n) {
    int i = blockIdx.x * blockDim.x + threadIdx.x;
    if (i < n) g_dinv[i] = rsqrtf((float)g_cnt[i]);
}
// two-pass chunked scan, single block of 1024
__global__ void scan_kernel(int n) {
    __shared__ int warp_sums[32];
    int tid = threadIdx.x;
    int chunk = (n + 1023) / 1024;
    int s = tid * chunk;
    int e = s + chunk; if (e > n) e = n; if (s > n) s = n;
    int sum = 0;
    for (int i = s; i < e; i++) sum += g_cnt[i];
    int lane = tid & 31, w = tid >> 5;
    int v = sum;
#pragma unroll
    for (int o = 1; o < 32; o <<= 1) {
        int t = __shfl_up_sync(0xFFFFFFFFu, v, o);
        if (lane >= o) v += t;
    }
    if (lane == 31) warp_sums[w] = v;
    __syncthreads();
    if (w == 0) {
        int x = warp_sums[lane];
#pragma unroll
        for (int o = 1; o < 32; o <<= 1) {
            int t = __shfl_up_sync(0xFFFFFFFFu, x, o);
            if (lane >= o) x += t;
        }
        warp_sums[lane] = x;
    }
    __syncthreads();
    int excl = v - sum + (w > 0 ? warp_sums[w - 1] : 0);
    int run = excl;
    for (int i = s; i < e; i++) {
        int c = g_cnt[i];
        g_rowptr[i] = run;
        g_cur[i] = run;
        run += c;
    }
    if (tid == 1023) g_rowptr[n] = run;
}
__global__ void fill_edges_kernel(const void* edge, int E) {
    int e = blockIdx.x * blockDim.x + threadIdx.x;
    if (e < E) {
        int src = ld_idx(edge, e);
        int dst = ld_idx(edge, (long)E + e);
        int pos = atomicAdd(&g_cur[dst], 1);
        g_col[pos] = src;
        g_wgt[pos] = g_dinv[src] * g_dinv[dst];
    }
}
__global__ void fill_loops_kernel(int n) {
    int i = blockIdx.x * blockDim.x + threadIdx.x;
    if (i < n) {
        int pos = atomicAdd(&g_cur[i], 1);
        g_col[pos] = i;
        g_wgt[pos] = g_dinv[i] * g_dinv[i];
    }
}

// ---------------- SpMM (fp16 gather, fp32 accumulate, fp16 out) ---------------
__device__ __forceinline__ void acc8(float* acc, const uint4& v, float w) {
    float2 f0 = __half22float2(*(const half2*)&v.x);
    float2 f1 = __half22float2(*(const half2*)&v.y);
    float2 f2 = __half22float2(*(const half2*)&v.z);
    float2 f3 = __half22float2(*(const half2*)&v.w);
    acc[0] += w * f0.x; acc[1] += w * f0.y;
    acc[2] += w * f1.x; acc[3] += w * f1.y;
    acc[4] += w * f2.x; acc[5] += w * f2.y;
    acc[6] += w * f3.x; acc[7] += w * f3.y;
}

__global__ void spmm_h_kernel(const uint4* __restrict__ in, uint4* __restrict__ out,
                              const float* __restrict__ bias, int act, int W8, int n) {
    int node = blockIdx.x * blockDim.y + threadIdx.y;
    if (node >= n) return;
    int t = threadIdx.x;
    int s = g_rowptr[node], e = g_rowptr[node + 1];
    float acc[8];
#pragma unroll
    for (int j = 0; j < 8; j++) acc[j] = 0.f;
    int p = s;
    for (; p + 3 < e; p += 4) {
        int c0 = g_col[p], c1 = g_col[p + 1], c2 = g_col[p + 2], c3 = g_col[p + 3];
        float w0 = g_wgt[p], w1 = g_wgt[p + 1], w2 = g_wgt[p + 2], w3 = g_wgt[p + 3];
        uint4 v0 = in[(size_t)c0 * W8 + t];
        uint4 v1 = in[(size_t)c1 * W8 + t];
        uint4 v2 = in[(size_t)c2 * W8 + t];
        uint4 v3 = in[(size_t)c3 * W8 + t];
        acc8(acc, v0, w0); acc8(acc, v1, w1);
        acc8(acc, v2, w2); acc8(acc, v3, w3);
    }
    for (; p < e; p++) {
        uint4 v0 = in[(size_t)g_col[p] * W8 + t];
        acc8(acc, v0, g_wgt[p]);
    }
    if (bias) {
#pragma unroll
        for (int j = 0; j < 8; j++) acc[j] += bias[8 * t + j];
    }
    if (act == 1) {
#pragma unroll
        for (int j = 0; j < 8; j++) acc[j] = fmaxf(acc[j], 0.f);
    } else if (act == 2) {
#pragma unroll
        for (int j = 0; j < 8; j++) acc[j] = acc[j] > 0.f ? acc[j] : 0.01f * acc[j];
    }
    uint4 ov;
    half2 h0 = __float22half2_rn(make_float2(acc[0], acc[1]));
    half2 h1 = __float22half2_rn(make_float2(acc[2], acc[3]));
    half2 h2 = __float22half2_rn(make_float2(acc[4], acc[5]));
    half2 h3 = __float22half2_rn(make_float2(acc[6], acc[7]));
    ov.x = *(uint32_t*)&h0; ov.y = *(uint32_t*)&h1;
    ov.z = *(uint32_t*)&h2; ov.w = *(uint32_t*)&h3;
    out[(size_t)node * W8 + t] = ov;
}

// fp32 scalar SpMM for final layer (W=32)
__global__ void spmm_kernel32(const float* __restrict__ in, float* __restrict__ out,
                              const float* __restrict__ bias, int act) {
    int node = blockIdx.x;
    int tid = threadIdx.x;
    int s = g_rowptr[node], e = g_rowptr[node + 1];
    float acc = 0.f;
    int p = s;
    for (; p + 1 < e; p += 2) {
        int c0 = g_col[p], c1 = g_col[p + 1];
        float w0 = g_wgt[p], w1 = g_wgt[p + 1];
        acc += w0 * in[(size_t)c0 * 32 + tid] + w1 * in[(size_t)c1 * 32 + tid];
    }
    if (p < e) acc += g_wgt[p] * in[(size_t)g_col[p] * 32 + tid];
    float v = acc;
    if (bias) v += bias[tid];
    if (act == 1) v = fmaxf(v, 0.f);
    else if (act == 2) v = (v > 0.f) ? v : 0.01f * v;
    out[(size_t)node * 32 + tid] = v;
}

// ---------------- x -> fp16 convert -------------------------------------------
__global__ void f2h_kernel(const float2* __restrict__ in, uint32_t* __restrict__ out,
                           long total2) {
    long i = (long)blockIdx.x * blockDim.x + threadIdx.x;
    if (i < total2) {
        float2 v = in[i];
        half2 h = __float22half2_rn(v);
        out[i] = *(uint32_t*)&h;
    }
}

// ---------------- fused weight transpose + fp16 split -------------------------
struct TParams { const float* W[9]; };
__global__ void transpose_all_kernel(TParams tp, float* wt9) {
    int l = blockIdx.z;
    int K = d_widths[l], N = d_widths[l + 1];
    int k0 = blockIdx.x * 32, n0 = blockIdx.y * 32;
    if (k0 >= K || n0 >= N) return;
    const float* W = tp.W[l];
    float* Wt = wt9 + (size_t)l * WMAX * WMAX;
    __shared__ float t[32][33];
    int x = threadIdx.x, y = threadIdx.y;
    for (int i = y; i < 32; i += 8) {
        int k = k0 + i, nn = n0 + x;
        t[i][x] = (k < K && nn < N) ? W[(size_t)k * N + nn] : 0.f;
    }
    __syncthreads();
    for (int i = y; i < 32; i += 8) {
        int nn = n0 + i, k = k0 + x;
        if (nn < N && k < K) Wt[(size_t)nn * K + k] = t[x][i];
    }
}
__global__ void split_w_kernel(const float* __restrict__ wt9,
                               uint32_t* __restrict__ whi, uint32_t* __restrict__ wlo,
                               int total_words) {
    int i = blockIdx.x * blockDim.x + threadIdx.x;
    if (i < total_words) {
        uint32_t h, l;
        split2h(wt9[2 * i], wt9[2 * i + 1], h, l);
        whi[i] = h;
        wlo[i] = l;
    }
}

// ---------------- 2xFP16 mma.sync GEMM (m16n8k16), cp.async pipelined ---------
// C = A(fp16) * (Whi + Wlo)^T, fp32 accumulate. BM=128, BN=128, BK=32.
#define S4 20
#define PLANE_WORDS (128 * S4)
#define STAGE_WORDS (3 * PLANE_WORDS)          // A, Bhi, Blo
#define GEMM_SMEM_BYTES (2 * STAGE_WORDS * 4)  // 61440 B double buffered

__device__ __forceinline__ void mma16h(float* d, const uint32_t* a, const uint32_t* b) {
    asm volatile(
        "mma.sync.aligned.m16n8k16.row.col.f32.f16.f16.f32 "
        "{%0,%1,%2,%3}, {%4,%5,%6,%7}, {%8,%9}, {%0,%1,%2,%3};"
        : "+f"(d[0]), "+f"(d[1]), "+f"(d[2]), "+f"(d[3])
        : "r"(a[0]), "r"(a[1]), "r"(a[2]), "r"(a[3]), "r"(b[0]), "r"(b[1]));
}
__device__ __forceinline__ void cp_async16(uint32_t dst, const void* src, int sz) {
    asm volatile("cp.async.ca.shared.global [%0], [%1], 16, %2;"
                 :: "r"(dst), "l"(src), "r"(sz) : "memory");
}

// mode: 0 = fp32 out (C), 2 = fp16 out (Oh)
__global__ __launch_bounds__(256) void gemm_h2_kernel(
    const uint32_t* __restrict__ Ah,
    const uint32_t* __restrict__ Bhi, const uint32_t* __restrict__ Blo,
    const float* __restrict__ bias, float* __restrict__ C,
    uint32_t* __restrict__ Oh,
    int M, int K, int Nfull, int act, int mode)
{
    extern __shared__ uint32_t smw[];
    uint32_t sb = smem_u32(smw);
    int tid = threadIdx.x;
    int wid = tid >> 5, lid = tid & 31;
    int wm = wid >> 2;
    int wn = wid & 3;
    int g  = lid >> 2;
    int tg = lid & 3;
    int m0 = blockIdx.y * 128;
    int n0 = blockIdx.x * 128;
    int Kw = K >> 1;

    float acc[4][4][4];
#pragma unroll
    for (int mi = 0; mi < 4; mi++)
#pragma unroll
        for (int ni = 0; ni < 4; ni++)
#pragma unroll
            for (int q = 0; q < 4; q++) acc[mi][ni][q] = 0.f;

    int KT = K >> 5;

    auto load_tile = [&](int kt, int b) {
        int kw = kt << 4;
        uint32_t base = sb + (uint32_t)(b * STAGE_WORDS) * 4u;
#pragma unroll
        for (int q = 0; q < 2; q++) {
            int i = tid + q * 256;
            int r = i >> 2, c = i & 3;
            uint32_t doff = (uint32_t)(r * S4 + c * 4) * 4u;
            bool okA = (m0 + r) < M;
            cp_async16(base + doff, Ah + (size_t)(m0 + r) * Kw + kw + c * 4, okA ? 16 : 0);
            bool okB = (n0 + r) < Nfull;
            size_t sB = (size_t)(n0 + r) * Kw + kw + c * 4;
            cp_async16(base + PLANE_WORDS * 4u + doff, Bhi + sB, okB ? 16 : 0);
            cp_async16(base + 2u * PLANE_WORDS * 4u + doff, Blo + sB, okB ? 16 : 0);
        }
    };

    load_tile(0, 0);
    asm volatile("cp.async.commit_group;" ::: "memory");
    if (KT > 1) load_tile(1, 1);
    asm volatile("cp.async.commit_group;" ::: "memory");

    for (int kt = 0; kt < KT; kt++) {
        asm volatile("cp.async.wait_group 1;" ::: "memory");
        __syncthreads();
        const uint32_t* AH = smw + (kt & 1) * STAGE_WORDS;
        const uint32_t* BH = AH + PLANE_WORDS;
        const uint32_t* BL = BH + PLANE_WORDS;

#pragma unroll
        for (int kk = 0; kk < 2; kk++) {
            int kb = kk * 8;
            uint32_t ah[4][4], bh[4][2], bl[4][2];
#pragma unroll
            for (int mi = 0; mi < 4; mi++) {
                int rb = wm * 64 + mi * 16;
                int o0 = (rb + g) * S4 + kb + tg;
                int o1 = (rb + g + 8) * S4 + kb + tg;
                ah[mi][0] = AH[o0]; ah[mi][1] = AH[o1];
                ah[mi][2] = AH[o0 + 4]; ah[mi][3] = AH[o1 + 4];
            }
#pragma unroll
            for (int ni = 0; ni < 4; ni++) {
                int nb = wn * 32 + ni * 8;
                int o = (nb + g) * S4 + kb + tg;
                bh[ni][0] = BH[o]; bh[ni][1] = BH[o + 4];
                bl[ni][0] = BL[o]; bl[ni][1] = BL[o + 4];
            }
#pragma unroll
            for (int mi = 0; mi < 4; mi++)
#pragma unroll
                for (int ni = 0; ni < 4; ni++) {
                    mma16h(acc[mi][ni], ah[mi], bh[ni]);
                    mma16h(acc[mi][ni], ah[mi], bl[ni]);
                }
        }
        __syncthreads();
        if (kt + 2 < KT) load_tile(kt + 2, kt & 1);
        asm volatile("cp.async.commit_group;" ::: "memory");
    }

    // epilogue
#pragma unroll
    for (int mi = 0; mi < 4; mi++) {
        int row0 = m0 + wm * 64 + mi * 16 + g;
        int row1 = row0 + 8;
#pragma unroll
        for (int ni = 0; ni < 4; ni++) {
            int col = n0 + wn * 32 + ni * 8 + 2 * tg;
            if (col >= Nfull) continue;
            float bx = 0.f, by = 0.f;
            if (bias) { bx = bias[col]; by = bias[col + 1]; }
#pragma unroll
            for (int h = 0; h < 2; h++) {
                int row = h ? row1 : row0;
                if (row >= M) continue;
                float vx = acc[mi][ni][h * 2 + 0] + bx;
                float vy = acc[mi][ni][h * 2 + 1] + by;
                if (act == 1) { vx = fmaxf(vx, 0.f); vy = fmaxf(vy, 0.f); }
                else if (act == 2) {
                    vx = vx > 0.f ? vx : 0.01f * vx;
                    vy = vy > 0.f ? vy : 0.01f * vy;
                }
                if (mode == 2) {
                    half2 hv = __float22half2_rn(make_float2(vx, vy));
                    Oh[(size_t)row * (Nfull >> 1) + (col >> 1)] = *(uint32_t*)&hv;
                } else {
                    *(float2*)(C + (size_t)row * Nfull + col) = make_float2(vx, vy);
                }
            }
        }
    }
}

// ---------------- mean pool ---------------------------------------------------
__global__ void zero_pool_kernel() {
    int i = blockIdx.x * blockDim.x + threadIdx.x;
    if (i < N_GRAPHS * 32) g_pool[i] = 0.f;
    if (i < N_GRAPHS) g_pcnt[i] = 0;
}
__global__ void pool_cnt_kernel(const void* batch, int n) {
    int i = blockIdx.x * blockDim.x + threadIdx.x;
    if (i < n) atomicAdd(&g_pcnt[ld_idx(batch, i)], 1);
}
__global__ void pool_sum_kernel(const float* __restrict__ h, const void* batch, int n) {
    int idx = blockIdx.x * blockDim.x + threadIdx.x;
    if (idx < n * 32) {
        int node = idx >> 5;
        int c = idx & 31;
        int b = ld_idx(batch, node);
        atomicAdd(&g_pool[b * 32 + c], h[(size_t)node * 32 + c]);
    }
}
__global__ void pool_fin_kernel(float* out) {
    int i = blockIdx.x * blockDim.x + threadIdx.x;
    if (i < N_GRAPHS * 32) {
        int b = i >> 5;
        out[i] = g_pool[i] / fmaxf((float)g_pcnt[b], 1.0f);
    }
}

// ---------------- host driver --------------------------------------------------
static inline int cdiv(int a, int b) { return (a + b - 1) / b; }

static void spmm_h_launch(const uint4* in, uint4* out,
                          const float* bias, int act, int W, int n) {
    int W8 = W / 8;
    int ypb = 128 / W8; if (ypb < 1) ypb = 1;
    dim3 blk(W8, ypb);
    spmm_h_kernel<<<cdiv(n, ypb), blk>>>(in, out, bias, act, W8, n);
}

extern "C" void kernel_launch(void* const* d_in, const int* in_sizes, int n_in,
                              void* d_out, int out_size) {
    const float* x     = (const float*)d_in[0];
    const void*  edge  = d_in[1];
    const void*  batch = d_in[2];
    TParams tp;
    const float* bl[9];
    for (int i = 0; i < 9; i++) {
        tp.W[i] = (const float*)d_in[3 + 2 * i];
        bl[i]   = (const float*)d_in[4 + 2 * i];
    }
    int n = in_sizes[2];
    int E = in_sizes[1] / 2;

    float *F, *out32, *wt9;
    uint4 *H0, *H1, *Ht;
    uint32_t *whi, *wlo;
    cudaGetSymbolAddress((void**)&F,     g_F);
    cudaGetSymbolAddress((void**)&out32, g_out32);
    cudaGetSymbolAddress((void**)&H0,    g_H0);
    cudaGetSymbolAddress((void**)&H1,    g_H1);
    cudaGetSymbolAddress((void**)&Ht,    g_Ht);
    cudaGetSymbolAddress((void**)&wt9,   g_wt9);
    cudaGetSymbolAddress((void**)&whi,   g_whi);
    cudaGetSymbolAddress((void**)&wlo,   g_wlo);

    cudaFuncSetAttribute(gemm_h2_kernel, cudaFuncAttributeMaxDynamicSharedMemorySize,
                         GEMM_SMEM_BYTES);

    // --- CSR build + weight transpose/split + x->fp16 ---
    detect_kernel<<<1, 1>>>(edge);
    transpose_all_kernel<<<dim3(16, 16, 9), dim3(32, 8)>>>(tp, wt9);
    split_w_kernel<<<cdiv(9 * WMAX * WMAX / 2, 256), 256>>>(wt9, whi, wlo, 9 * WMAX * WMAX / 2);
    f2h_kernel<<<cdiv(n * 64, 256), 256>>>((const float2*)x, (uint32_t*)H0, (long)n * 64);
    init_cnt_kernel<<<cdiv(n, 256), 256>>>(n);
    count_kernel<<<cdiv(E, 256), 256>>>(edge, E);
    dinv_kernel<<<cdiv(n, 256), 256>>>(n);
    scan_kernel<<<1, 1024>>>(n);
    fill_edges_kernel<<<cdiv(E, 256), 256>>>(edge, E);
    fill_loops_kernel<<<cdiv(n, 256), 256>>>(n);

    // --- layers ---
    static const int widths[10]  = {128, 128, 256, 384, 512, 512, 384, 256, 128, 32};
    static const int acts[9]     = {1, 1, 2, 1, 2, 2, 1, 1, 0};
    static const int aggfirst[9] = {1, 1, 1, 1, 1, 0, 0, 0, 0};

    const uint4* Hin = H0;
    uint4* pong[2] = {H1, H0};
    int pp = 0;
    for (int l = 0; l < 9; l++) {
        int K = widths[l], N = widths[l + 1];
        const uint32_t* wh  = whi + (size_t)l * WMAX * WMAX / 2;
        const uint32_t* wl_ = wlo + (size_t)l * WMAX * WMAX / 2;
        dim3 grid(cdiv(N, 128), cdiv(n, 128));
        uint4* Hout = pong[pp];
        if (aggfirst[l]) {
            spmm_h_launch(Hin, Ht, nullptr, 0, K, n);
            gemm_h2_kernel<<<grid, 256, GEMM_SMEM_BYTES>>>(
                (const uint32_t*)Ht, wh, wl_, bl[l], nullptr, (uint32_t*)Hout,
                n, K, N, acts[l], 2);
            Hin = Hout; pp ^= 1;
        } else if (l < 8) {
            gemm_h2_kernel<<<grid, 256, GEMM_SMEM_BYTES>>>(
                (const uint32_t*)Hin, wh, wl_, nullptr, nullptr, (uint32_t*)Ht,
                n, K, N, 0, 2);
            spmm_h_launch(Ht, Hout, bl[l], acts[l], N, n);
            Hin = Hout; pp ^= 1;
        } else {
            gemm_h2_kernel<<<grid, 256, GEMM_SMEM_BYTES>>>(
                (const uint32_t*)Hin, wh, wl_, nullptr, F, nullptr,
                n, K, N, 0, 0);
            spmm_kernel32<<<n, 32>>>(F, out32, bl[l], 0);
        }
    }

    // --- pool ---
    zero_pool_kernel<<<cdiv(N_GRAPHS * 32, 256), 256>>>();
    pool_cnt_kernel<<<cdiv(n, 256), 256>>>(batch, n);
    pool_sum_kernel<<<cdiv(n * 32, 256), 256>>>(out32, batch, n);
    pool_fin_kernel<<<cdiv(N_GRAPHS * 32, 256), 256>>>((float*)d_out);
}

// round 8
// speedup vs baseline: 3.6214x; 1.1748x over previous
#include <cuda_runtime.h>
#include <cuda_fp16.h>
#include <cstdint>

#define N_MAX   50000
#define E_MAX   1700000
#define WMAX    512
#define N_GRAPHS 64

// ---------------- scratch (device globals) ----------------------------------
__device__ float    g_F[(size_t)N_MAX * 32];                   // final gemm out fp32
__device__ uint4    g_H0[(size_t)N_MAX * WMAX / 8];            // fp16 activations (ping)
__device__ uint4    g_H1[(size_t)N_MAX * WMAX / 8];            // fp16 activations (pong)
__device__ uint4    g_Ht[(size_t)N_MAX * WMAX / 8];            // fp16 temp (agg)
__device__ float    g_wt9[(size_t)9 * WMAX * WMAX];            // fp32 transposed weights
__device__ uint32_t g_wh[(size_t)9 * WMAX * WMAX / 2];         // fp16 weights (packed x2)
__device__ float    g_dinv[N_MAX];
__device__ int      g_cnt[N_MAX];
__device__ int      g_rowptr[N_MAX + 1];
__device__ int      g_cur[N_MAX];
__device__ int      g_col[E_MAX];
__device__ float    g_wgt[E_MAX];
__device__ float    g_pool[N_GRAPHS * 32];
__device__ int      g_pcnt[N_GRAPHS];
__device__ int      g_is64;

__device__ const int d_widths[10] = {128, 128, 256, 384, 512, 512, 384, 256, 128, 32};

// ---------------- helpers -----------------------------------------------------
__device__ __forceinline__ uint32_t smem_u32(const void* p) {
    uint32_t a;
    asm("{ .reg .u64 t; cvta.to.shared.u64 t, %1; cvt.u32.u64 %0, t; }" : "=r"(a) : "l"(p));
    return a;
}
__device__ __forceinline__ int ld_idx(const void* p, long i) {
    if (g_is64) return (int)((const long long*)p)[i];
    return ((const int*)p)[i];
}
__global__ void detect_kernel(const void* edge) {
    const int* p = (const int*)edge;
    bool is64 = true;
    for (int i = 0; i < 8; i++)
        if (p[2 * i + 1] != 0) is64 = false;
    g_is64 = is64 ? 1 : 0;
}

// ---------------- setup: cnt=1, pool=0, pcnt=0 --------------------------------
__global__ void setup_kernel(int n) {
    int i = blockIdx.x * blockDim.x + threadIdx.x;
    if (i < n) g_cnt[i] = 1;
    if (i < N_GRAPHS * 32) g_pool[i] = 0.f;
    if (i < N_GRAPHS) g_pcnt[i] = 0;
}
__global__ void count_kernel(const void* edge, int E) {
    int e = blockIdx.x * blockDim.x + threadIdx.x;
    if (e < E) atomicAdd(&g_cnt[ld_idx(edge, (long)E + e)], 1);
}
__global__ void dinv_kernel(int n) {
    int i = blockIdx.x * blockDim.x + threadIdx.x;
    if (i < n) g_dinv[i] = rsqrtf((float)g_cnt[i]);
}
// two-pass chunked scan, single block of 1024
__global__ void scan_kernel(int n) {
    __shared__ int warp_sums[32];
    int tid = threadIdx.x;
    int chunk = (n + 1023) / 1024;
    int s = tid * chunk;
    int e = s + chunk; if (e > n) e = n; if (s > n) s = n;
    int sum = 0;
    for (int i = s; i < e; i++) sum += g_cnt[i];
    int lane = tid & 31, w = tid >> 5;
    int v = sum;
#pragma unroll
    for (int o = 1; o < 32; o <<= 1) {
        int t = __shfl_up_sync(0xFFFFFFFFu, v, o);
        if (lane >= o) v += t;
    }
    if (lane == 31) warp_sums[w] = v;
    __syncthreads();
    if (w == 0) {
        int x = warp_sums[lane];
#pragma unroll
        for (int o = 1; o < 32; o <<= 1) {
            int t = __shfl_up_sync(0xFFFFFFFFu, x, o);
            if (lane >= o) x += t;
        }
        warp_sums[lane] = x;
    }
    __syncthreads();
    int excl = v - sum + (w > 0 ? warp_sums[w - 1] : 0);
    int run = excl;
    for (int i = s; i < e; i++) {
        int c = g_cnt[i];
        g_rowptr[i] = run;
        g_cur[i] = run;
        run += c;
    }
    if (tid == 1023) g_rowptr[n] = run;
}
__global__ void fill_edges_kernel(const void* edge, int E) {
    int e = blockIdx.x * blockDim.x + threadIdx.x;
    if (e < E) {
        int src = ld_idx(edge, e);
        int dst = ld_idx(edge, (long)E + e);
        int pos = atomicAdd(&g_cur[dst], 1);
        g_col[pos] = src;
        g_wgt[pos] = g_dinv[src] * g_dinv[dst];
    }
}
__global__ void fill_loops_kernel(int n) {
    int i = blockIdx.x * blockDim.x + threadIdx.x;
    if (i < n) {
        int pos = atomicAdd(&g_cur[i], 1);
        g_col[pos] = i;
        g_wgt[pos] = g_dinv[i] * g_dinv[i];
    }
}

// ---------------- SpMM (fp16 gather, fp32 accumulate, fp16 out) ---------------
__device__ __forceinline__ void acc8(float* acc, const uint4& v, float w) {
    float2 f0 = __half22float2(*(const half2*)&v.x);
    float2 f1 = __half22float2(*(const half2*)&v.y);
    float2 f2 = __half22float2(*(const half2*)&v.z);
    float2 f3 = __half22float2(*(const half2*)&v.w);
    acc[0] += w * f0.x; acc[1] += w * f0.y;
    acc[2] += w * f1.x; acc[3] += w * f1.y;
    acc[4] += w * f2.x; acc[5] += w * f2.y;
    acc[6] += w * f3.x; acc[7] += w * f3.y;
}

__global__ void spmm_h_kernel(const uint4* __restrict__ in, uint4* __restrict__ out,
                              const float* __restrict__ bias, int act, int W8, int n) {
    int node = blockIdx.x * blockDim.y + threadIdx.y;
    if (node >= n) return;
    int t = threadIdx.x;
    int s = g_rowptr[node], e = g_rowptr[node + 1];
    float acc[8];
#pragma unroll
    for (int j = 0; j < 8; j++) acc[j] = 0.f;
    int p = s;
    for (; p + 3 < e; p += 4) {
        int c0 = g_col[p], c1 = g_col[p + 1], c2 = g_col[p + 2], c3 = g_col[p + 3];
        float w0 = g_wgt[p], w1 = g_wgt[p + 1], w2 = g_wgt[p + 2], w3 = g_wgt[p + 3];
        uint4 v0 = in[(size_t)c0 * W8 + t];
        uint4 v1 = in[(size_t)c1 * W8 + t];
        uint4 v2 = in[(size_t)c2 * W8 + t];
        uint4 v3 = in[(size_t)c3 * W8 + t];
        acc8(acc, v0, w0); acc8(acc, v1, w1);
        acc8(acc, v2, w2); acc8(acc, v3, w3);
    }
    for (; p < e; p++) {
        uint4 v0 = in[(size_t)g_col[p] * W8 + t];
        acc8(acc, v0, g_wgt[p]);
    }
    if (bias) {
#pragma unroll
        for (int j = 0; j < 8; j++) acc[j] += bias[8 * t + j];
    }
    if (act == 1) {
#pragma unroll
        for (int j = 0; j < 8; j++) acc[j] = fmaxf(acc[j], 0.f);
    } else if (act == 2) {
#pragma unroll
        for (int j = 0; j < 8; j++) acc[j] = acc[j] > 0.f ? acc[j] : 0.01f * acc[j];
    }
    uint4 ov;
    half2 h0 = __float22half2_rn(make_float2(acc[0], acc[1]));
    half2 h1 = __float22half2_rn(make_float2(acc[2], acc[3]));
    half2 h2 = __float22half2_rn(make_float2(acc[4], acc[5]));
    half2 h3 = __float22half2_rn(make_float2(acc[6], acc[7]));
    ov.x = *(uint32_t*)&h0; ov.y = *(uint32_t*)&h1;
    ov.z = *(uint32_t*)&h2; ov.w = *(uint32_t*)&h3;
    out[(size_t)node * W8 + t] = ov;
}

// final layer: SpMM at W=32 fused with pooling atomics
__global__ void spmm_pool_kernel(const float* __restrict__ in, const void* batch,
                                 const float* __restrict__ bias, int n) {
    int node = blockIdx.x * blockDim.y + threadIdx.y;
    if (node >= n) return;
    int tid = threadIdx.x;
    int s = g_rowptr[node], e = g_rowptr[node + 1];
    float acc = 0.f;
    int p = s;
    for (; p + 1 < e; p += 2) {
        int c0 = g_col[p], c1 = g_col[p + 1];
        float w0 = g_wgt[p], w1 = g_wgt[p + 1];
        acc += w0 * in[(size_t)c0 * 32 + tid] + w1 * in[(size_t)c1 * 32 + tid];
    }
    if (p < e) acc += g_wgt[p] * in[(size_t)g_col[p] * 32 + tid];
    float v = acc + bias[tid];
    int b = ld_idx(batch, node);
    atomicAdd(&g_pool[b * 32 + tid], v);
}

// ---------------- x -> fp16 convert -------------------------------------------
__global__ void f2h_kernel(const float2* __restrict__ in, uint32_t* __restrict__ out,
                           long total2) {
    long i = (long)blockIdx.x * blockDim.x + threadIdx.x;
    if (i < total2) {
        float2 v = in[i];
        half2 h = __float22half2_rn(v);
        out[i] = *(uint32_t*)&h;
    }
}

// ---------------- fused weight transpose + fp16 round -------------------------
struct TParams { const float* W[9]; };
__global__ void transpose_all_kernel(TParams tp, float* wt9) {
    int l = blockIdx.z;
    int K = d_widths[l], N = d_widths[l + 1];
    int k0 = blockIdx.x * 32, n0 = blockIdx.y * 32;
    if (k0 >= K || n0 >= N) return;
    const float* W = tp.W[l];
    float* Wt = wt9 + (size_t)l * WMAX * WMAX;
    __shared__ float t[32][33];
    int x = threadIdx.x, y = threadIdx.y;
    for (int i = y; i < 32; i += 8) {
        int k = k0 + i, nn = n0 + x;
        t[i][x] = (k < K && nn < N) ? W[(size_t)k * N + nn] : 0.f;
    }
    __syncthreads();
    for (int i = y; i < 32; i += 8) {
        int nn = n0 + i, k = k0 + x;
        if (nn < N && k < K) Wt[(size_t)nn * K + k] = t[x][i];
    }
}
__global__ void round_w_kernel(const float* __restrict__ wt9,
                               uint32_t* __restrict__ wh, int total_words) {
    int i = blockIdx.x * blockDim.x + threadIdx.x;
    if (i < total_words) {
        half2 h = __float22half2_rn(make_float2(wt9[2 * i], wt9[2 * i + 1]));
        wh[i] = *(uint32_t*)&h;
    }
}

// ---------------- FP16 mma.sync GEMM (m16n8k16), cp.async pipelined -----------
// C = A(fp16) * W(fp16)^T, fp32 accumulate. BM=128, BN=128, BK=32.
#define S4 20
#define PLANE_WORDS (128 * S4)
#define STAGE_WORDS (2 * PLANE_WORDS)          // A, B
#define GEMM_SMEM_BYTES (2 * STAGE_WORDS * 4)  // 40960 B double buffered

__device__ __forceinline__ void mma16h(float* d, const uint32_t* a, const uint32_t* b) {
    asm volatile(
        "mma.sync.aligned.m16n8k16.row.col.f32.f16.f16.f32 "
        "{%0,%1,%2,%3}, {%4,%5,%6,%7}, {%8,%9}, {%0,%1,%2,%3};"
        : "+f"(d[0]), "+f"(d[1]), "+f"(d[2]), "+f"(d[3])
        : "r"(a[0]), "r"(a[1]), "r"(a[2]), "r"(a[3]), "r"(b[0]), "r"(b[1]));
}
__device__ __forceinline__ void cp_async16(uint32_t dst, const void* src, int sz) {
    asm volatile("cp.async.ca.shared.global [%0], [%1], 16, %2;"
                 :: "r"(dst), "l"(src), "r"(sz) : "memory");
}

// mode: 0 = fp32 out (C), 2 = fp16 out (Oh)
__global__ __launch_bounds__(256) void gemm_h1_kernel(
    const uint32_t* __restrict__ Ah, const uint32_t* __restrict__ Bh,
    const float* __restrict__ bias, float* __restrict__ C,
    uint32_t* __restrict__ Oh,
    int M, int K, int Nfull, int act, int mode)
{
    extern __shared__ uint32_t smw[];
    uint32_t sb = smem_u32(smw);
    int tid = threadIdx.x;
    int wid = tid >> 5, lid = tid & 31;
    int wm = wid >> 2;
    int wn = wid & 3;
    int g  = lid >> 2;
    int tg = lid & 3;
    int m0 = blockIdx.y * 128;
    int n0 = blockIdx.x * 128;
    int Kw = K >> 1;

    float acc[4][4][4];
#pragma unroll
    for (int mi = 0; mi < 4; mi++)
#pragma unroll
        for (int ni = 0; ni < 4; ni++)
#pragma unroll
            for (int q = 0; q < 4; q++) acc[mi][ni][q] = 0.f;

    int KT = K >> 5;

    auto load_tile = [&](int kt, int b) {
        int kw = kt << 4;
        uint32_t base = sb + (uint32_t)(b * STAGE_WORDS) * 4u;
#pragma unroll
        for (int q = 0; q < 2; q++) {
            int i = tid + q * 256;
            int r = i >> 2, c = i & 3;
            uint32_t doff = (uint32_t)(r * S4 + c * 4) * 4u;
            bool okA = (m0 + r) < M;
            cp_async16(base + doff, Ah + (size_t)(m0 + r) * Kw + kw + c * 4, okA ? 16 : 0);
            bool okB = (n0 + r) < Nfull;
            cp_async16(base + PLANE_WORDS * 4u + doff,
                       Bh + (size_t)(n0 + r) * Kw + kw + c * 4, okB ? 16 : 0);
        }
    };

    load_tile(0, 0);
    asm volatile("cp.async.commit_group;" ::: "memory");
    if (KT > 1) load_tile(1, 1);
    asm volatile("cp.async.commit_group;" ::: "memory");

    for (int kt = 0; kt < KT; kt++) {
        asm volatile("cp.async.wait_group 1;" ::: "memory");
        __syncthreads();
        const uint32_t* AH = smw + (kt & 1) * STAGE_WORDS;
        const uint32_t* BH = AH + PLANE_WORDS;

#pragma unroll
        for (int kk = 0; kk < 2; kk++) {
            int kb = kk * 8;
            uint32_t ah[4][4], bh[4][2];
#pragma unroll
            for (int mi = 0; mi < 4; mi++) {
                int rb = wm * 64 + mi * 16;
                int o0 = (rb + g) * S4 + kb + tg;
                int o1 = (rb + g + 8) * S4 + kb + tg;
                ah[mi][0] = AH[o0]; ah[mi][1] = AH[o1];
                ah[mi][2] = AH[o0 + 4]; ah[mi][3] = AH[o1 + 4];
            }
#pragma unroll
            for (int ni = 0; ni < 4; ni++) {
                int nb = wn * 32 + ni * 8;
                int o = (nb + g) * S4 + kb + tg;
                bh[ni][0] = BH[o]; bh[ni][1] = BH[o + 4];
            }
#pragma unroll
            for (int mi = 0; mi < 4; mi++)
#pragma unroll
                for (int ni = 0; ni < 4; ni++)
                    mma16h(acc[mi][ni], ah[mi], bh[ni]);
        }
        __syncthreads();
        if (kt + 2 < KT) load_tile(kt + 2, kt & 1);
        asm volatile("cp.async.commit_group;" ::: "memory");
    }

    // epilogue
#pragma unroll
    for (int mi = 0; mi < 4; mi++) {
        int row0 = m0 + wm * 64 + mi * 16 + g;
        int row1 = row0 + 8;
#pragma unroll
        for (int ni = 0; ni < 4; ni++) {
            int col = n0 + wn * 32 + ni * 8 + 2 * tg;
            if (col >= Nfull) continue;
            float bx = 0.f, by = 0.f;
            if (bias) { bx = bias[col]; by = bias[col + 1]; }
#pragma unroll
            for (int h = 0; h < 2; h++) {
                int row = h ? row1 : row0;
                if (row >= M) continue;
                float vx = acc[mi][ni][h * 2 + 0] + bx;
                float vy = acc[mi][ni][h * 2 + 1] + by;
                if (act == 1) { vx = fmaxf(vx, 0.f); vy = fmaxf(vy, 0.f); }
                else if (act == 2) {
                    vx = vx > 0.f ? vx : 0.01f * vx;
                    vy = vy > 0.f ? vy : 0.01f * vy;
                }
                if (mode == 2) {
                    half2 hv = __float22half2_rn(make_float2(vx, vy));
                    Oh[(size_t)row * (Nfull >> 1) + (col >> 1)] = *(uint32_t*)&hv;
                } else {
                    *(float2*)(C + (size_t)row * Nfull + col) = make_float2(vx, vy);
                }
            }
        }
    }
}

// ---------------- pool tail ----------------------------------------------------
__global__ void pool_cnt_kernel(const void* batch, int n) {
    int i = blockIdx.x * blockDim.x + threadIdx.x;
    if (i < n) atomicAdd(&g_pcnt[ld_idx(batch, i)], 1);
}
__global__ void pool_fin_kernel(float* out) {
    int i = blockIdx.x * blockDim.x + threadIdx.x;
    if (i < N_GRAPHS * 32) {
        int b = i >> 5;
        out[i] = g_pool[i] / fmaxf((float)g_pcnt[b], 1.0f);
    }
}

// ---------------- host driver --------------------------------------------------
static inline int cdiv(int a, int b) { return (a + b - 1) / b; }

static void spmm_h_launch(const uint4* in, uint4* out,
                          const float* bias, int act, int W, int n) {
    int W8 = W / 8;
    int ypb = 128 / W8; if (ypb < 1) ypb = 1;
    dim3 blk(W8, ypb);
    spmm_h_kernel<<<cdiv(n, ypb), blk>>>(in, out, bias, act, W8, n);
}

extern "C" void kernel_launch(void* const* d_in, const int* in_sizes, int n_in,
                              void* d_out, int out_size) {
    const float* x     = (const float*)d_in[0];
    const void*  edge  = d_in[1];
    const void*  batch = d_in[2];
    TParams tp;
    const float* bl[9];
    for (int i = 0; i < 9; i++) {
        tp.W[i] = (const float*)d_in[3 + 2 * i];
        bl[i]   = (const float*)d_in[4 + 2 * i];
    }
    int n = in_sizes[2];
    int E = in_sizes[1] / 2;

    float *F, *wt9;
    uint4 *H0, *H1, *Ht;
    uint32_t *wh;
    cudaGetSymbolAddress((void**)&F,   g_F);
    cudaGetSymbolAddress((void**)&H0,  g_H0);
    cudaGetSymbolAddress((void**)&H1,  g_H1);
    cudaGetSymbolAddress((void**)&Ht,  g_Ht);
    cudaGetSymbolAddress((void**)&wt9, g_wt9);
    cudaGetSymbolAddress((void**)&wh,  g_wh);

    cudaFuncSetAttribute(gemm_h1_kernel, cudaFuncAttributeMaxDynamicSharedMemorySize,
                         GEMM_SMEM_BYTES);

    // --- CSR build + weight transpose/round + x->fp16 ---
    detect_kernel<<<1, 1>>>(edge);
    transpose_all_kernel<<<dim3(16, 16, 9), dim3(32, 8)>>>(tp, wt9);
    round_w_kernel<<<cdiv(9 * WMAX * WMAX / 2, 256), 256>>>(wt9, wh, 9 * WMAX * WMAX / 2);
    f2h_kernel<<<cdiv(n * 64, 256), 256>>>((const float2*)x, (uint32_t*)H0, (long)n * 64);
    setup_kernel<<<cdiv(n, 256), 256>>>(n);
    count_kernel<<<cdiv(E, 256), 256>>>(edge, E);
    pool_cnt_kernel<<<cdiv(n, 256), 256>>>(batch, n);
    dinv_kernel<<<cdiv(n, 256), 256>>>(n);
    scan_kernel<<<1, 1024>>>(n);
    fill_edges_kernel<<<cdiv(E, 256), 256>>>(edge, E);
    fill_loops_kernel<<<cdiv(n, 256), 256>>>(n);

    // --- layers ---
    static const int widths[10]  = {128, 128, 256, 384, 512, 512, 384, 256, 128, 32};
    static const int acts[9]     = {1, 1, 2, 1, 2, 2, 1, 1, 0};
    static const int aggfirst[9] = {1, 1, 1, 1, 1, 0, 0, 0, 0};

    const uint4* Hin = H0;
    uint4* pong[2] = {H1, H0};
    int pp = 0;
    for (int l = 0; l < 9; l++) {
        int K = widths[l], N = widths[l + 1];
        const uint32_t* wl = wh + (size_t)l * WMAX * WMAX / 2;
        dim3 grid(cdiv(N, 128), cdiv(n, 128));
        uint4* Hout = pong[pp];
        if (aggfirst[l]) {
            spmm_h_launch(Hin, Ht, nullptr, 0, K, n);
            gemm_h1_kernel<<<grid, 256, GEMM_SMEM_BYTES>>>(
                (const uint32_t*)Ht, wl, bl[l], nullptr, (uint32_t*)Hout,
                n, K, N, acts[l], 2);
            Hin = Hout; pp ^= 1;
        } else if (l < 8) {
            gemm_h1_kernel<<<grid, 256, GEMM_SMEM_BYTES>>>(
                (const uint32_t*)Hin, wl, nullptr, nullptr, (uint32_t*)Ht,
                n, K, N, 0, 2);
            spmm_h_launch(Ht, Hout, bl[l], acts[l], N, n);
            Hin = Hout; pp ^= 1;
        } else {
            gemm_h1_kernel<<<grid, 256, GEMM_SMEM_BYTES>>>(
                (const uint32_t*)Hin, wl, nullptr, F, nullptr,
                n, K, N, 0, 0);
            spmm_pool_kernel<<<cdiv(n, 4), dim3(32, 4)>>>(F, batch, bl[8], n);
        }
    }

    // --- pool finalize ---
    pool_fin_kernel<<<cdiv(N_GRAPHS * 32, 256), 256>>>((float*)d_out);
}

// round 10
// speedup vs baseline: 3.7215x; 1.0276x over previous
#include <cuda_runtime.h>
#include <cuda_fp16.h>
#include <cstdint>

#define N_MAX   50000
#define E_MAX   1700000
#define WMAX    512
#define N_GRAPHS 64

// ---------------- scratch (device globals) ----------------------------------
__device__ float    g_F[(size_t)N_MAX * 32];                   // final gemm out fp32
__device__ uint4    g_H0[(size_t)N_MAX * WMAX / 8];            // fp16 activations (ping)
__device__ uint4    g_H1[(size_t)N_MAX * WMAX / 8];            // fp16 activations (pong)
__device__ uint4    g_Ht[(size_t)N_MAX * WMAX / 8];            // fp16 temp (agg)
__device__ uint4    g_whh[(size_t)9 * WMAX * WMAX / 8];        // fp16 weights [N][K], 9 layers
__device__ float    g_dinv[N_MAX];
__device__ int      g_cnt[N_MAX];
__device__ int      g_rowptr[N_MAX + 1];
__device__ int      g_cur[N_MAX];
__device__ int      g_col[E_MAX];
__device__ float    g_wgt[E_MAX];
__device__ float    g_pool[N_GRAPHS * 32];
__device__ int      g_pcnt[N_GRAPHS];
__device__ int      g_is64;

__device__ const int d_widths[10] = {128, 128, 256, 384, 512, 512, 384, 256, 128, 32};

// ---------------- helpers -----------------------------------------------------
__device__ __forceinline__ uint32_t smem_u32(const void* p) {
    uint32_t a;
    asm("{ .reg .u64 t; cvta.to.shared.u64 t, %1; cvt.u32.u64 %0, t; }" : "=r"(a) : "l"(p));
    return a;
}
__device__ __forceinline__ int ld_idx(const void* p, long i) {
    if (g_is64) return (int)((const long long*)p)[i];
    return ((const int*)p)[i];
}
__global__ void detect_kernel(const void* edge) {
    const int* p = (const int*)edge;
    bool is64 = true;
    for (int i = 0; i < 8; i++)
        if (p[2 * i + 1] != 0) is64 = false;
    g_is64 = is64 ? 1 : 0;
}

// ---------------- setup: cnt=1, pool=0, pcnt=0 --------------------------------
__global__ void setup_kernel(int n) {
    int i = blockIdx.x * blockDim.x + threadIdx.x;
    if (i < n) g_cnt[i] = 1;
    if (i < N_GRAPHS * 32) g_pool[i] = 0.f;
    if (i < N_GRAPHS) g_pcnt[i] = 0;
}
// merged: edge-degree count + per-graph node count
__global__ void count_pool_kernel(const void* edge, const void* batch, int E, int n) {
    int i = blockIdx.x * blockDim.x + threadIdx.x;
    if (i < E) atomicAdd(&g_cnt[ld_idx(edge, (long)E + i)], 1);
    if (i < n) atomicAdd(&g_pcnt[ld_idx(batch, i)], 1);
}
// two-pass chunked scan, single block of 1024; also computes dinv
__global__ void scan_kernel(int n) {
    __shared__ int warp_sums[32];
    int tid = threadIdx.x;
    int chunk = (n + 1023) / 1024;
    int s = tid * chunk;
    int e = s + chunk; if (e > n) e = n; if (s > n) s = n;
    int sum = 0;
    for (int i = s; i < e; i++) sum += g_cnt[i];
    int lane = tid & 31, w = tid >> 5;
    int v = sum;
#pragma unroll
    for (int o = 1; o < 32; o <<= 1) {
        int t = __shfl_up_sync(0xFFFFFFFFu, v, o);
        if (lane >= o) v += t;
    }
    if (lane == 31) warp_sums[w] = v;
    __syncthreads();
    if (w == 0) {
        int x = warp_sums[lane];
#pragma unroll
        for (int o = 1; o < 32; o <<= 1) {
            int t = __shfl_up_sync(0xFFFFFFFFu, x, o);
            if (lane >= o) x += t;
        }
        warp_sums[lane] = x;
    }
    __syncthreads();
    int excl = v - sum + (w > 0 ? warp_sums[w - 1] : 0);
    int run = excl;
    for (int i = s; i < e; i++) {
        int c = g_cnt[i];
        g_rowptr[i] = run;
        g_cur[i] = run;
        g_dinv[i] = rsqrtf((float)c);
        run += c;
    }
    if (tid == 1023) g_rowptr[n] = run;
}
// merged: fill edges + self loops
__global__ void fill_kernel(const void* edge, int E, int n) {
    int i = blockIdx.x * blockDim.x + threadIdx.x;
    if (i < E) {
        int src = ld_idx(edge, i);
        int dst = ld_idx(edge, (long)E + i);
        int pos = atomicAdd(&g_cur[dst], 1);
        g_col[pos] = src;
        g_wgt[pos] = g_dinv[src] * g_dinv[dst];
    } else if (i < E + n) {
        int node = i - E;
        int pos = atomicAdd(&g_cur[node], 1);
        g_col[pos] = node;
        g_wgt[pos] = g_dinv[node] * g_dinv[node];
    }
}

// ---------------- SpMM (fp16 gather, fp32 accumulate, fp16 out) ---------------
__device__ __forceinline__ void acc8(float* acc, const uint4& v, float w) {
    float2 f0 = __half22float2(*(const half2*)&v.x);
    float2 f1 = __half22float2(*(const half2*)&v.y);
    float2 f2 = __half22float2(*(const half2*)&v.z);
    float2 f3 = __half22float2(*(const half2*)&v.w);
    acc[0] += w * f0.x; acc[1] += w * f0.y;
    acc[2] += w * f1.x; acc[3] += w * f1.y;
    acc[4] += w * f2.x; acc[5] += w * f2.y;
    acc[6] += w * f3.x; acc[7] += w * f3.y;
}

__global__ void spmm_h_kernel(const uint4* __restrict__ in, uint4* __restrict__ out,
                              const float* __restrict__ bias, int act, int W8, int n) {
    int node = blockIdx.x * blockDim.y + threadIdx.y;
    if (node >= n) return;
    int t = threadIdx.x;
    int s = g_rowptr[node], e = g_rowptr[node + 1];
    float acc[8];
#pragma unroll
    for (int j = 0; j < 8; j++) acc[j] = 0.f;
    int p = s;
    for (; p + 3 < e; p += 4) {
        int c0 = g_col[p], c1 = g_col[p + 1], c2 = g_col[p + 2], c3 = g_col[p + 3];
        float w0 = g_wgt[p], w1 = g_wgt[p + 1], w2 = g_wgt[p + 2], w3 = g_wgt[p + 3];
        uint4 v0 = in[(size_t)c0 * W8 + t];
        uint4 v1 = in[(size_t)c1 * W8 + t];
        uint4 v2 = in[(size_t)c2 * W8 + t];
        uint4 v3 = in[(size_t)c3 * W8 + t];
        acc8(acc, v0, w0); acc8(acc, v1, w1);
        acc8(acc, v2, w2); acc8(acc, v3, w3);
    }
    for (; p < e; p++) {
        uint4 v0 = in[(size_t)g_col[p] * W8 + t];
        acc8(acc, v0, g_wgt[p]);
    }
    if (bias) {
#pragma unroll
        for (int j = 0; j < 8; j++) acc[j] += bias[8 * t + j];
    }
    if (act == 1) {
#pragma unroll
        for (int j = 0; j < 8; j++) acc[j] = fmaxf(acc[j], 0.f);
    } else if (act == 2) {
#pragma unroll
        for (int j = 0; j < 8; j++) acc[j] = acc[j] > 0.f ? acc[j] : 0.01f * acc[j];
    }
    uint4 ov;
    half2 h0 = __float22half2_rn(make_float2(acc[0], acc[1]));
    half2 h1 = __float22half2_rn(make_float2(acc[2], acc[3]));
    half2 h2 = __float22half2_rn(make_float2(acc[4], acc[5]));
    half2 h3 = __float22half2_rn(make_float2(acc[6], acc[7]));
    ov.x = *(uint32_t*)&h0; ov.y = *(uint32_t*)&h1;
    ov.z = *(uint32_t*)&h2; ov.w = *(uint32_t*)&h3;
    out[(size_t)node * W8 + t] = ov;
}

// final layer: SpMM at W=32 fused with pooling atomics
__global__ void spmm_pool_kernel(const float* __restrict__ in, const void* batch,
                                 const float* __restrict__ bias, int n) {
    int node = blockIdx.x * blockDim.y + threadIdx.y;
    if (node >= n) return;
    int tid = threadIdx.x;
    int s = g_rowptr[node], e = g_rowptr[node + 1];
    float acc = 0.f;
    int p = s;
    for (; p + 1 < e; p += 2) {
        int c0 = g_col[p], c1 = g_col[p + 1];
        float w0 = g_wgt[p], w1 = g_wgt[p + 1];
        acc += w0 * in[(size_t)c0 * 32 + tid] + w1 * in[(size_t)c1 * 32 + tid];
    }
    if (p < e) acc += g_wgt[p] * in[(size_t)g_col[p] * 32 + tid];
    float v = acc + bias[tid];
    int b = ld_idx(batch, node);
    atomicAdd(&g_pool[b * 32 + tid], v);
}

// ---------------- x -> fp16 convert -------------------------------------------
__global__ void f2h_kernel(const float2* __restrict__ in, uint32_t* __restrict__ out,
                           long total2) {
    long i = (long)blockIdx.x * blockDim.x + threadIdx.x;
    if (i < total2) {
        float2 v = in[i];
        half2 h = __float22half2_rn(v);
        out[i] = *(uint32_t*)&h;
    }
}

// ---------------- fused weight transpose -> fp16 directly ---------------------
struct TParams { const float* W[9]; };
__global__ void transpose_all_kernel(TParams tp, __half* whh) {
    int l = blockIdx.z;
    int K = d_widths[l], N = d_widths[l + 1];
    int k0 = blockIdx.x * 32, n0 = blockIdx.y * 32;
    if (k0 >= K || n0 >= N) return;
    const float* W = tp.W[l];
    __half* Wt = whh + (size_t)l * WMAX * WMAX;
    __shared__ float t[32][33];
    int x = threadIdx.x, y = threadIdx.y;
    for (int i = y; i < 32; i += 8) {
        int k = k0 + i, nn = n0 + x;
        t[i][x] = (k < K && nn < N) ? W[(size_t)k * N + nn] : 0.f;
    }
    __syncthreads();
    for (int i = y; i < 32; i += 8) {
        int nn = n0 + i, k = k0 + x;
        if (nn < N && k < K) Wt[(size_t)nn * K + k] = __float2half_rn(t[x][i]);
    }
}

// ---------------- FP16 mma.sync GEMM (m16n8k16), cp.async pipelined -----------
// C = A(fp16) * W(fp16)^T, fp32 accumulate. BM=128, BN=128, BK=32.
#define S4 20
#define PLANE_WORDS (128 * S4)
#define STAGE_WORDS (2 * PLANE_WORDS)          // A, B
#define GEMM_SMEM_BYTES (2 * STAGE_WORDS * 4)  // 40960 B double buffered

__device__ __forceinline__ void mma16h(float* d, const uint32_t* a, const uint32_t* b) {
    asm volatile(
        "mma.sync.aligned.m16n8k16.row.col.f32.f16.f16.f32 "
        "{%0,%1,%2,%3}, {%4,%5,%6,%7}, {%8,%9}, {%0,%1,%2,%3};"
        : "+f"(d[0]), "+f"(d[1]), "+f"(d[2]), "+f"(d[3])
        : "r"(a[0]), "r"(a[1]), "r"(a[2]), "r"(a[3]), "r"(b[0]), "r"(b[1]));
}
__device__ __forceinline__ void cp_async16(uint32_t dst, const void* src, int sz) {
    asm volatile("cp.async.ca.shared.global [%0], [%1], 16, %2;"
                 :: "r"(dst), "l"(src), "r"(sz) : "memory");
}

// mode: 0 = fp32 out (C), 2 = fp16 out (Oh)
__global__ __launch_bounds__(256, 2) void gemm_h1_kernel(
    const uint32_t* __restrict__ Ah, const uint32_t* __restrict__ Bh,
    const float* __restrict__ bias, float* __restrict__ C,
    uint32_t* __restrict__ Oh,
    int M, int K, int Nfull, int act, int mode)
{
    extern __shared__ uint32_t smw[];
    uint32_t sb = smem_u32(smw);
    int tid = threadIdx.x;
    int wid = tid >> 5, lid = tid & 31;
    int wm = wid >> 2;
    int wn = wid & 3;
    int g  = lid >> 2;
    int tg = lid & 3;
    int m0 = blockIdx.y * 128;
    int n0 = blockIdx.x * 128;
    int Kw = K >> 1;

    float acc[4][4][4];
#pragma unroll
    for (int mi = 0; mi < 4; mi++)
#pragma unroll
        for (int ni = 0; ni < 4; ni++)
#pragma unroll
            for (int q = 0; q < 4; q++) acc[mi][ni][q] = 0.f;

    int KT = K >> 5;

    auto load_tile = [&](int kt, int b) {
        int kw = kt << 4;
        uint32_t base = sb + (uint32_t)(b * STAGE_WORDS) * 4u;
#pragma unroll
        for (int q = 0; q < 2; q++) {
            int i = tid + q * 256;
            int r = i >> 2, c = i & 3;
            uint32_t doff = (uint32_t)(r * S4 + c * 4) * 4u;
            bool okA = (m0 + r) < M;
            cp_async16(base + doff, Ah + (size_t)(m0 + r) * Kw + kw + c * 4, okA ? 16 : 0);
            bool okB = (n0 + r) < Nfull;
            cp_async16(base + PLANE_WORDS * 4u + doff,
                       Bh + (size_t)(n0 + r) * Kw + kw + c * 4, okB ? 16 : 0);
        }
    };

    load_tile(0, 0);
    asm volatile("cp.async.commit_group;" ::: "memory");
    if (KT > 1) load_tile(1, 1);
    asm volatile("cp.async.commit_group;" ::: "memory");

    for (int kt = 0; kt < KT; kt++) {
        asm volatile("cp.async.wait_group 1;" ::: "memory");
        __syncthreads();
        const uint32_t* AH = smw + (kt & 1) * STAGE_WORDS;
        const uint32_t* BH = AH + PLANE_WORDS;

#pragma unroll
        for (int kk = 0; kk < 2; kk++) {
            int kb = kk * 8;
            uint32_t ah[4][4], bh[4][2];
#pragma unroll
            for (int mi = 0; mi < 4; mi++) {
                int rb = wm * 64 + mi * 16;
                int o0 = (rb + g) * S4 + kb + tg;
                int o1 = (rb + g + 8) * S4 + kb + tg;
                ah[mi][0] = AH[o0]; ah[mi][1] = AH[o1];
                ah[mi][2] = AH[o0 + 4]; ah[mi][3] = AH[o1 + 4];
            }
#pragma unroll
            for (int ni = 0; ni < 4; ni++) {
                int nb = wn * 32 + ni * 8;
                int o = (nb + g) * S4 + kb + tg;
                bh[ni][0] = BH[o]; bh[ni][1] = BH[o + 4];
            }
#pragma unroll
            for (int mi = 0; mi < 4; mi++)
#pragma unroll
                for (int ni = 0; ni < 4; ni++)
                    mma16h(acc[mi][ni], ah[mi], bh[ni]);
        }
        __syncthreads();
        if (kt + 2 < KT) load_tile(kt + 2, kt & 1);
        asm volatile("cp.async.commit_group;" ::: "memory");
    }

    // epilogue
#pragma unroll
    for (int mi = 0; mi < 4; mi++) {
        int row0 = m0 + wm * 64 + mi * 16 + g;
        int row1 = row0 + 8;
#pragma unroll
        for (int ni = 0; ni < 4; ni++) {
            int col = n0 + wn * 32 + ni * 8 + 2 * tg;
            if (col >= Nfull) continue;
            float bx = 0.f, by = 0.f;
            if (bias) { bx = bias[col]; by = bias[col + 1]; }
#pragma unroll
            for (int h = 0; h < 2; h++) {
                int row = h ? row1 : row0;
                if (row >= M) continue;
                float vx = acc[mi][ni][h * 2 + 0] + bx;
                float vy = acc[mi][ni][h * 2 + 1] + by;
                if (act == 1) { vx = fmaxf(vx, 0.f); vy = fmaxf(vy, 0.f); }
                else if (act == 2) {
                    vx = vx > 0.f ? vx : 0.01f * vx;
                    vy = vy > 0.f ? vy : 0.01f * vy;
                }
                if (mode == 2) {
                    half2 hv = __float22half2_rn(make_float2(vx, vy));
                    Oh[(size_t)row * (Nfull >> 1) + (col >> 1)] = *(uint32_t*)&hv;
                } else {
                    *(float2*)(C + (size_t)row * Nfull + col) = make_float2(vx, vy);
                }
            }
        }
    }
}

// ---------------- pool tail ----------------------------------------------------
__global__ void pool_fin_kernel(float* out) {
    int i = blockIdx.x * blockDim.x + threadIdx.x;
    if (i < N_GRAPHS * 32) {
        int b = i >> 5;
        out[i] = g_pool[i] / fmaxf((float)g_pcnt[b], 1.0f);
    }
}

// ---------------- host driver --------------------------------------------------
static inline int cdiv(int a, int b) { return (a + b - 1) / b; }

static void spmm_h_launch(const uint4* in, uint4* out,
                          const float* bias, int act, int W, int n) {
    int W8 = W / 8;
    int ypb = 128 / W8; if (ypb < 1) ypb = 1;
    dim3 blk(W8, ypb);
    spmm_h_kernel<<<cdiv(n, ypb), blk>>>(in, out, bias, act, W8, n);
}

extern "C" void kernel_launch(void* const* d_in, const int* in_sizes, int n_in,
                              void* d_out, int out_size) {
    const float* x     = (const float*)d_in[0];
    const void*  edge  = d_in[1];
    const void*  batch = d_in[2];
    TParams tp;
    const float* bl[9];
    for (int i = 0; i < 9; i++) {
        tp.W[i] = (const float*)d_in[3 + 2 * i];
        bl[i]   = (const float*)d_in[4 + 2 * i];
    }
    int n = in_sizes[2];
    int E = in_sizes[1] / 2;

    float *F;
    uint4 *H0, *H1, *Ht, *whh;
    cudaGetSymbolAddress((void**)&F,   g_F);
    cudaGetSymbolAddress((void**)&H0,  g_H0);
    cudaGetSymbolAddress((void**)&H1,  g_H1);
    cudaGetSymbolAddress((void**)&Ht,  g_Ht);
    cudaGetSymbolAddress((void**)&whh, g_whh);

    cudaFuncSetAttribute(gemm_h1_kernel, cudaFuncAttributeMaxDynamicSharedMemorySize,
                         GEMM_SMEM_BYTES);

    // --- setup: CSR build + fp16 weight transpose + x->fp16 (6 kernels) ---
    detect_kernel<<<1, 1>>>(edge);
    transpose_all_kernel<<<dim3(16, 16, 9), dim3(32, 8)>>>(tp, (__half*)whh);
    f2h_kernel<<<cdiv(n * 64, 256), 256>>>((const float2*)x, (uint32_t*)H0, (long)n * 64);
    setup_kernel<<<cdiv(n, 256), 256>>>(n);
    count_pool_kernel<<<cdiv(E > n ? E : n, 256), 256>>>(edge, batch, E, n);
    scan_kernel<<<1, 1024>>>(n);
    fill_kernel<<<cdiv(E + n, 256), 256>>>(edge, E, n);

    // --- layers ---
    static const int widths[10]  = {128, 128, 256, 384, 512, 512, 384, 256, 128, 32};
    static const int acts[9]     = {1, 1, 2, 1, 2, 2, 1, 1, 0};
    static const int aggfirst[9] = {1, 1, 1, 1, 1, 0, 0, 0, 0};

    const uint4* Hin = H0;
    uint4* pong[2] = {H1, H0};
    int pp = 0;
    for (int l = 0; l < 9; l++) {
        int K = widths[l], N = widths[l + 1];
        const uint32_t* wl = (const uint32_t*)whh + (size_t)l * WMAX * WMAX / 2;
        dim3 grid(cdiv(N, 128), cdiv(n, 128));
        uint4* Hout = pong[pp];
        if (aggfirst[l]) {
            spmm_h_launch(Hin, Ht, nullptr, 0, K, n);
            gemm_h1_kernel<<<grid, 256, GEMM_SMEM_BYTES>>>(
                (const uint32_t*)Ht, wl, bl[l], nullptr, (uint32_t*)Hout,
                n, K, N, acts[l], 2);
            Hin = Hout; pp ^= 1;
        } else if (l < 8) {
            gemm_h1_kernel<<<grid, 256, GEMM_SMEM_BYTES>>>(
                (const uint32_t*)Hin, wl, nullptr, nullptr, (uint32_t*)Ht,
                n, K, N, 0, 2);
            spmm_h_launch(Ht, Hout, bl[l], acts[l], N, n);
            Hin = Hout; pp ^= 1;
        } else {
            gemm_h1_kernel<<<grid, 256, GEMM_SMEM_BYTES>>>(
                (const uint32_t*)Hin, wl, nullptr, F, nullptr,
                n, K, N, 0, 0);
            spmm_pool_kernel<<<cdiv(n, 4), dim3(32, 4)>>>(F, batch, bl[8], n);
        }
    }

    // --- pool finalize ---
    pool_fin_kernel<<<cdiv(N_GRAPHS * 32, 256), 256>>>((float*)d_out);
}